// round 1
// baseline (speedup 1.0000x reference)
#include <cuda_runtime.h>
#include <math.h>

#define DM   512
#define HN   8
#define DKH  32
#define BSZ  4
#define LSEQ 2048
#define INNER 256            // HN*DKH
#define MROWS (BSZ*LSEQ)     // 8192

// ---------------- scratch (device globals; no allocation allowed) ----------
__device__ float g_Qh[BSZ*HN*LSEQ*DKH];   // [n][h][l][d]
__device__ float g_Kh[BSZ*HN*LSEQ*DKH];
__device__ float g_Vh[BSZ*HN*LSEQ*DKH];
__device__ float g_AO[MROWS*INNER];       // merged attn out [m][h*32+d]
__device__ float g_X [MROWS*DM];          // fc + residual (LN input)

// ---------------- projection GEMM: C[M,256] = X[M,512] @ W^T + b ------------
// 64x64 tile, BK=16, 256 threads, 4x4 micro-tile. Epilogue scatters to
// head-major layout: c = d*H + h  ->  Out[n][h][l][d].
__global__ __launch_bounds__(256) void proj_gemm(const float* __restrict__ X,
                                                 const float* __restrict__ W,
                                                 const float* __restrict__ bias,
                                                 int which) {
    __shared__ float Xs[16][64];
    __shared__ float Ws[16][64];
    const int K = DM;
    const int t = threadIdx.x;
    const int m0 = blockIdx.y * 64;
    const int n0 = blockIdx.x * 64;
    const int lrow = t >> 2;          // 0..63
    const int lk   = (t & 3) * 4;     // 0,4,8,12
    const int tx = t & 15, ty = t >> 4;

    float acc[4][4] = {};
    for (int k0 = 0; k0 < K; k0 += 16) {
        float4 xv = *(const float4*)(X + (size_t)(m0 + lrow) * K + k0 + lk);
        float4 wv = *(const float4*)(W + (size_t)(n0 + lrow) * K + k0 + lk);
        Xs[lk+0][lrow] = xv.x; Xs[lk+1][lrow] = xv.y;
        Xs[lk+2][lrow] = xv.z; Xs[lk+3][lrow] = xv.w;
        Ws[lk+0][lrow] = wv.x; Ws[lk+1][lrow] = wv.y;
        Ws[lk+2][lrow] = wv.z; Ws[lk+3][lrow] = wv.w;
        __syncthreads();
#pragma unroll
        for (int kk = 0; kk < 16; kk++) {
            float4 a = *(const float4*)&Xs[kk][ty*4];
            float4 b = *(const float4*)&Ws[kk][tx*4];
            float av[4] = {a.x, a.y, a.z, a.w};
            float bv[4] = {b.x, b.y, b.z, b.w};
#pragma unroll
            for (int i = 0; i < 4; i++)
#pragma unroll
                for (int j = 0; j < 4; j++) acc[i][j] += av[i] * bv[j];
        }
        __syncthreads();
    }
    float* Out = (which == 0) ? g_Qh : (which == 1) ? g_Kh : g_Vh;
#pragma unroll
    for (int i = 0; i < 4; i++) {
        int m = m0 + ty*4 + i;
        int n = m >> 11;            // m / 2048
        int l = m & 2047;
#pragma unroll
        for (int j = 0; j < 4; j++) {
            int c = n0 + tx*4 + j;
            float v = acc[i][j] + bias[c];
            int d = c >> 3;          // c / H
            int h = c & 7;           // c % H
            Out[((((size_t)n*HN + h)*LSEQ + l)*DKH) + d] = v;
        }
    }
}

// ---------------- flash attention: 1 thread = 1 query row ------------------
__global__ __launch_bounds__(128) void attn_kernel() {
    const int n = blockIdx.z, h = blockIdx.y;
    const int tid = threadIdx.x;
    const int l = blockIdx.x * 128 + tid;
    const float scale = 0.17677669529663687f;   // 1/sqrt(32)

    const size_t slab = (((size_t)n*HN + h) * LSEQ) * DKH;
    const float* Kbase = g_Kh + slab;
    const float* Vbase = g_Vh + slab;

    float4 qv[8];
    {
        const float4* qp = (const float4*)(g_Qh + slab + (size_t)l * DKH);
#pragma unroll
        for (int u = 0; u < 8; u++) qv[u] = qp[u];
    }

    __shared__ float Ks[32*32];
    __shared__ float Vs[32*32];

    float mrun = -1e30f, lsum = 0.0f;
    float4 accv[8];
#pragma unroll
    for (int u = 0; u < 8; u++) accv[u] = make_float4(0.f, 0.f, 0.f, 0.f);

    for (int kt = 0; kt < LSEQ; kt += 32) {
        __syncthreads();
        {   // stage 32x32 K and V rows (contiguous 1024 floats each)
            const float4* Ksrc = (const float4*)(Kbase + (size_t)kt * DKH);
            const float4* Vsrc = (const float4*)(Vbase + (size_t)kt * DKH);
            float4* Kd = (float4*)Ks; float4* Vd = (float4*)Vs;
            Kd[tid] = Ksrc[tid]; Kd[tid+128] = Ksrc[tid+128];
            Vd[tid] = Vsrc[tid]; Vd[tid+128] = Vsrc[tid+128];
        }
        __syncthreads();

        float s[32];
        float tmax = -1e30f;
#pragma unroll 4
        for (int j = 0; j < 32; j++) {
            const float4* kr = (const float4*)(Ks + j*32);
            float sum = 0.f;
#pragma unroll
            for (int u = 0; u < 8; u++) {
                float4 kk = kr[u];
                sum += qv[u].x*kk.x + qv[u].y*kk.y + qv[u].z*kk.z + qv[u].w*kk.w;
            }
            sum *= scale;
            s[j] = sum;
            tmax = fmaxf(tmax, sum);
        }
        float mnew = fmaxf(mrun, tmax);
        float corr = __expf(mrun - mnew);
        lsum *= corr;
#pragma unroll
        for (int u = 0; u < 8; u++) {
            accv[u].x *= corr; accv[u].y *= corr;
            accv[u].z *= corr; accv[u].w *= corr;
        }
#pragma unroll 4
        for (int j = 0; j < 32; j++) {
            float p = __expf(s[j] - mnew);
            lsum += p;
            const float4* vr = (const float4*)(Vs + j*32);
#pragma unroll
            for (int u = 0; u < 8; u++) {
                float4 vv = vr[u];
                accv[u].x += p*vv.x; accv[u].y += p*vv.y;
                accv[u].z += p*vv.z; accv[u].w += p*vv.w;
            }
        }
        mrun = mnew;
    }

    const float inv = 1.0f / lsum;
    float4* op = (float4*)(g_AO + ((size_t)n*LSEQ + l)*INNER + h*DKH);
#pragma unroll
    for (int u = 0; u < 8; u++) {
        float4 r = accv[u];
        r.x *= inv; r.y *= inv; r.z *= inv; r.w *= inv;
        op[u] = r;
    }
}

// ---------------- FC GEMM + bias + residual: X = AO @ Wfc^T + bfc + q ------
__global__ __launch_bounds__(256) void fc_gemm(const float* __restrict__ Wfc,
                                               const float* __restrict__ bfc,
                                               const float* __restrict__ qres) {
    __shared__ float As[16][64];
    __shared__ float Ws[16][64];
    const int K = INNER;   // 256
    const int t = threadIdx.x;
    const int m0 = blockIdx.y * 64;
    const int n0 = blockIdx.x * 64;
    const int lrow = t >> 2;
    const int lk   = (t & 3) * 4;
    const int tx = t & 15, ty = t >> 4;

    float acc[4][4] = {};
    for (int k0 = 0; k0 < K; k0 += 16) {
        float4 av = *(const float4*)(g_AO + (size_t)(m0 + lrow) * K + k0 + lk);
        float4 wv = *(const float4*)(Wfc  + (size_t)(n0 + lrow) * K + k0 + lk);
        As[lk+0][lrow] = av.x; As[lk+1][lrow] = av.y;
        As[lk+2][lrow] = av.z; As[lk+3][lrow] = av.w;
        Ws[lk+0][lrow] = wv.x; Ws[lk+1][lrow] = wv.y;
        Ws[lk+2][lrow] = wv.z; Ws[lk+3][lrow] = wv.w;
        __syncthreads();
#pragma unroll
        for (int kk = 0; kk < 16; kk++) {
            float4 a = *(const float4*)&As[kk][ty*4];
            float4 b = *(const float4*)&Ws[kk][tx*4];
            float aa[4] = {a.x, a.y, a.z, a.w};
            float bb[4] = {b.x, b.y, b.z, b.w};
#pragma unroll
            for (int i = 0; i < 4; i++)
#pragma unroll
                for (int j = 0; j < 4; j++) acc[i][j] += aa[i] * bb[j];
        }
        __syncthreads();
    }
#pragma unroll
    for (int i = 0; i < 4; i++) {
        int m = m0 + ty*4 + i;
#pragma unroll
        for (int j = 0; j < 4; j++) {
            int c = n0 + tx*4 + j;
            float v = acc[i][j] + bfc[c] + qres[(size_t)m*DM + c];
            g_X[(size_t)m*DM + c] = v;
        }
    }
}

// ---------------- LayerNorm: one warp per 512-elem row ---------------------
__global__ __launch_bounds__(256) void ln_kernel(const float* __restrict__ gamma,
                                                 const float* __restrict__ beta,
                                                 float* __restrict__ out) {
    const int gw = (blockIdx.x * blockDim.x + threadIdx.x) >> 5;
    const int lane = threadIdx.x & 31;
    if (gw >= MROWS) return;

    const float4* xp = (const float4*)(g_X + (size_t)gw * DM);
    float4 v[4];
#pragma unroll
    for (int i = 0; i < 4; i++) v[i] = xp[lane + 32*i];

    float sum = 0.f;
#pragma unroll
    for (int i = 0; i < 4; i++) sum += v[i].x + v[i].y + v[i].z + v[i].w;
#pragma unroll
    for (int o = 16; o; o >>= 1) sum += __shfl_xor_sync(0xffffffffu, sum, o);
    const float mean = sum * (1.0f / DM);

    float sq = 0.f;
#pragma unroll
    for (int i = 0; i < 4; i++) {
        float dx = v[i].x - mean, dy = v[i].y - mean;
        float dz = v[i].z - mean, dw = v[i].w - mean;
        sq += dx*dx + dy*dy + dz*dz + dw*dw;
    }
#pragma unroll
    for (int o = 16; o; o >>= 1) sq += __shfl_xor_sync(0xffffffffu, sq, o);
    const float rstd = rsqrtf(sq * (1.0f / DM) + 1e-5f);

    const float4* gp = (const float4*)gamma;
    const float4* bp = (const float4*)beta;
    float4* op = (float4*)(out + (size_t)gw * DM);
#pragma unroll
    for (int i = 0; i < 4; i++) {
        float4 g = gp[lane + 32*i];
        float4 b = bp[lane + 32*i];
        float4 r;
        r.x = (v[i].x - mean) * rstd * g.x + b.x;
        r.y = (v[i].y - mean) * rstd * g.y + b.y;
        r.z = (v[i].z - mean) * rstd * g.z + b.z;
        r.w = (v[i].w - mean) * rstd * g.w + b.w;
        op[lane + 32*i] = r;
    }
}

// ---------------- launch ---------------------------------------------------
extern "C" void kernel_launch(void* const* d_in, const int* in_sizes, int n_in,
                              void* d_out, int out_size) {
    const float* q     = (const float*)d_in[0];
    const float* k     = (const float*)d_in[1];
    const float* v     = (const float*)d_in[2];
    const float* Wq    = (const float*)d_in[3];
    const float* bq    = (const float*)d_in[4];
    const float* Wk    = (const float*)d_in[5];
    const float* bk    = (const float*)d_in[6];
    const float* Wv    = (const float*)d_in[7];
    const float* bv    = (const float*)d_in[8];
    const float* Wfc   = (const float*)d_in[9];
    const float* bfc   = (const float*)d_in[10];
    const float* gamma = (const float*)d_in[11];
    const float* beta  = (const float*)d_in[12];

    dim3 gp(INNER/64, MROWS/64);          // (4, 128)
    proj_gemm<<<gp, 256>>>(q, Wq, bq, 0);
    proj_gemm<<<gp, 256>>>(k, Wk, bk, 1);
    proj_gemm<<<gp, 256>>>(v, Wv, bv, 2);

    dim3 ga(LSEQ/128, HN, BSZ);           // (16, 8, 4)
    attn_kernel<<<ga, 128>>>();

    dim3 gf(DM/64, MROWS/64);             // (8, 128)
    fc_gemm<<<gf, 256>>>(Wfc, bfc, q);

    ln_kernel<<<MROWS/8, 256>>>(gamma, beta, (float*)d_out);
}

// round 2
// speedup vs baseline: 1.7459x; 1.7459x over previous
#include <cuda_runtime.h>
#include <math.h>

#define DM   512
#define HN   8
#define DKH  32
#define BSZ  4
#define LSEQ 2048
#define INNER 256            // HN*DKH
#define MROWS (BSZ*LSEQ)     // 8192

// ---------------- scratch (device globals; no allocation allowed) ----------
__device__ float g_Qh[BSZ*HN*LSEQ*DKH];   // [n][h][l][d]
__device__ float g_Kh[BSZ*HN*LSEQ*DKH];
__device__ float g_Vh[BSZ*HN*LSEQ*DKH];
__device__ float g_AO[MROWS*INNER];       // merged attn out [m][h*32+d]
__device__ float g_X [MROWS*DM];          // fc + residual (LN input)

// ---------------- mma helpers ----------------------------------------------
__device__ __forceinline__ unsigned f2tf(float f) {
    unsigned u;
    asm("cvt.rna.tf32.f32 %0, %1;" : "=r"(u) : "f"(f));
    return u;
}

__device__ __forceinline__ void mma_tf32(float c[4], const unsigned a[4], const unsigned b[2]) {
    asm volatile(
        "mma.sync.aligned.m16n8k8.row.col.f32.tf32.tf32.f32 "
        "{%0,%1,%2,%3}, {%4,%5,%6,%7}, {%8,%9}, {%0,%1,%2,%3};"
        : "+f"(c[0]), "+f"(c[1]), "+f"(c[2]), "+f"(c[3])
        : "r"(a[0]), "r"(a[1]), "r"(a[2]), "r"(a[3]),
          "r"(b[0]), "r"(b[1]));
}

// ---------------- projection GEMM: C[M,256] = X[M,512] @ W^T + b ------------
__global__ __launch_bounds__(256) void proj_gemm(const float* __restrict__ X,
                                                 const float* __restrict__ W,
                                                 const float* __restrict__ bias,
                                                 int which) {
    __shared__ float Xs[16][64];
    __shared__ float Ws[16][64];
    const int K = DM;
    const int t = threadIdx.x;
    const int m0 = blockIdx.y * 64;
    const int n0 = blockIdx.x * 64;
    const int lrow = t >> 2;
    const int lk   = (t & 3) * 4;
    const int tx = t & 15, ty = t >> 4;

    float acc[4][4] = {};
    for (int k0 = 0; k0 < K; k0 += 16) {
        float4 xv = *(const float4*)(X + (size_t)(m0 + lrow) * K + k0 + lk);
        float4 wv = *(const float4*)(W + (size_t)(n0 + lrow) * K + k0 + lk);
        Xs[lk+0][lrow] = xv.x; Xs[lk+1][lrow] = xv.y;
        Xs[lk+2][lrow] = xv.z; Xs[lk+3][lrow] = xv.w;
        Ws[lk+0][lrow] = wv.x; Ws[lk+1][lrow] = wv.y;
        Ws[lk+2][lrow] = wv.z; Ws[lk+3][lrow] = wv.w;
        __syncthreads();
#pragma unroll
        for (int kk = 0; kk < 16; kk++) {
            float4 a = *(const float4*)&Xs[kk][ty*4];
            float4 b = *(const float4*)&Ws[kk][tx*4];
            float av[4] = {a.x, a.y, a.z, a.w};
            float bv[4] = {b.x, b.y, b.z, b.w};
#pragma unroll
            for (int i = 0; i < 4; i++)
#pragma unroll
                for (int j = 0; j < 4; j++) acc[i][j] += av[i] * bv[j];
        }
        __syncthreads();
    }
    float* Out = (which == 0) ? g_Qh : (which == 1) ? g_Kh : g_Vh;
#pragma unroll
    for (int i = 0; i < 4; i++) {
        int m = m0 + ty*4 + i;
        int n = m >> 11;
        int l = m & 2047;
#pragma unroll
        for (int j = 0; j < 4; j++) {
            int c = n0 + tx*4 + j;
            float v = acc[i][j] + bias[c];
            int d = c >> 3;
            int h = c & 7;
            Out[((((size_t)n*HN + h)*LSEQ + l)*DKH) + d] = v;
        }
    }
}

// ---------------- flash attention (tf32 mma, FA2 style) --------------------
// CTA = one (n,h), 128 queries; 4 warps x 32 queries. 64-key tiles.
__global__ __launch_bounds__(128) void attn_mma() {
    const int n = blockIdx.z, h = blockIdx.y;
    const int tid  = threadIdx.x;
    const int warp = tid >> 5, lane = tid & 31;
    const int gid  = lane >> 2;          // group id (row within tile fragment)
    const int q4   = lane & 3;           // quad lane
    const int qbase = blockIdx.x * 128 + warp * 32;
    const float scale = 0.17677669529663687f;  // 1/sqrt(32)

    const size_t slab = (((size_t)n*HN + h) * LSEQ) * DKH;
    const float* Qg = g_Qh + slab;
    const float* Kg = g_Kh + slab;
    const float* Vg = g_Vh + slab;

    // padded smem: row stride 36 floats -> bank-conflict-free fragment loads
    __shared__ float Ks[64*36];
    __shared__ float Vs[64*36];

    // Q fragments (scale folded in), tf32
    unsigned qa[2][4][4];
#pragma unroll
    for (int mi = 0; mi < 2; mi++) {
        int r0 = qbase + mi*16 + gid;
#pragma unroll
        for (int kk = 0; kk < 4; kk++) {
            int c0 = kk*8 + q4;
            qa[mi][kk][0] = f2tf(Qg[(size_t)r0*32       + c0    ] * scale);
            qa[mi][kk][1] = f2tf(Qg[(size_t)(r0+8)*32   + c0    ] * scale);
            qa[mi][kk][2] = f2tf(Qg[(size_t)r0*32       + c0 + 4] * scale);
            qa[mi][kk][3] = f2tf(Qg[(size_t)(r0+8)*32   + c0 + 4] * scale);
        }
    }

    float o[2][4][4];
#pragma unroll
    for (int mi = 0; mi < 2; mi++)
#pragma unroll
        for (int nv = 0; nv < 4; nv++)
#pragma unroll
            for (int r = 0; r < 4; r++) o[mi][nv][r] = 0.f;
    float mrow[4] = {-1e30f, -1e30f, -1e30f, -1e30f};
    float lrow[4] = {0.f, 0.f, 0.f, 0.f};

    for (int kt = 0; kt < LSEQ; kt += 64) {
        __syncthreads();
        {   // stage 64x32 K and V tiles (row stride 36)
            int row = tid >> 1, half = (tid & 1) * 16;
            const float4* ks = (const float4*)(Kg + (size_t)(kt + row)*32 + half);
            const float4* vs = (const float4*)(Vg + (size_t)(kt + row)*32 + half);
            float4* kd = (float4*)(Ks + row*36 + half);
            float4* vd = (float4*)(Vs + row*36 + half);
            kd[0]=ks[0]; kd[1]=ks[1]; kd[2]=ks[2]; kd[3]=ks[3];
            vd[0]=vs[0]; vd[1]=vs[1]; vd[2]=vs[2]; vd[3]=vs[3];
        }
        __syncthreads();

        // ---- S = Q K^T (scaled) ----
        float s[2][8][4];
#pragma unroll
        for (int mi = 0; mi < 2; mi++)
#pragma unroll
            for (int ni = 0; ni < 8; ni++)
#pragma unroll
                for (int r = 0; r < 4; r++) s[mi][ni][r] = 0.f;

#pragma unroll
        for (int ni = 0; ni < 8; ni++) {
            int krow = ni*8 + gid;
#pragma unroll
            for (int kk = 0; kk < 4; kk++) {
                unsigned b[2];
                b[0] = f2tf(Ks[krow*36 + kk*8 + q4    ]);
                b[1] = f2tf(Ks[krow*36 + kk*8 + q4 + 4]);
                mma_tf32(s[0][ni], qa[0][kk], b);
                mma_tf32(s[1][ni], qa[1][kk], b);
            }
        }

        // ---- online softmax on fragments ----
#pragma unroll
        for (int mi = 0; mi < 2; mi++) {
#pragma unroll
            for (int rh = 0; rh < 2; rh++) {
                const int idx = mi*2 + rh;
                float tmax = -1e30f;
#pragma unroll
                for (int ni = 0; ni < 8; ni++)
                    tmax = fmaxf(tmax, fmaxf(s[mi][ni][2*rh], s[mi][ni][2*rh+1]));
                tmax = fmaxf(tmax, __shfl_xor_sync(0xffffffffu, tmax, 1));
                tmax = fmaxf(tmax, __shfl_xor_sync(0xffffffffu, tmax, 2));
                float mnew = fmaxf(mrow[idx], tmax);
                float corr = __expf(mrow[idx] - mnew);
                mrow[idx] = mnew;
                float lsum = lrow[idx] * corr;
#pragma unroll
                for (int nv = 0; nv < 4; nv++) {
                    o[mi][nv][2*rh]   *= corr;
                    o[mi][nv][2*rh+1] *= corr;
                }
#pragma unroll
                for (int ni = 0; ni < 8; ni++) {
                    float p0 = __expf(s[mi][ni][2*rh]   - mnew);
                    float p1 = __expf(s[mi][ni][2*rh+1] - mnew);
                    lsum += p0 + p1;
                    s[mi][ni][2*rh]   = p0;
                    s[mi][ni][2*rh+1] = p1;
                }
                lrow[idx] = lsum;
            }
        }

        // ---- permute P (accumulator layout -> A-operand layout), tf32 ----
        const int src0 = (lane & ~3) | (q4 >> 1);
        const int src1 = src0 + 2;
        const bool odd = (q4 & 1);
#pragma unroll
        for (int mi = 0; mi < 2; mi++) {
#pragma unroll
            for (int ni = 0; ni < 8; ni++) {
                unsigned u0 = f2tf(s[mi][ni][0]);
                unsigned u1 = f2tf(s[mi][ni][1]);
                unsigned u2 = f2tf(s[mi][ni][2]);
                unsigned u3 = f2tf(s[mi][ni][3]);
                unsigned t0  = __shfl_sync(0xffffffffu, u0, src0);
                unsigned t1  = __shfl_sync(0xffffffffu, u1, src0);
                unsigned t0b = __shfl_sync(0xffffffffu, u0, src1);
                unsigned t1b = __shfl_sync(0xffffffffu, u1, src1);
                unsigned a0 = odd ? t1  : t0;
                unsigned a2 = odd ? t1b : t0b;
                t0  = __shfl_sync(0xffffffffu, u2, src0);
                t1  = __shfl_sync(0xffffffffu, u3, src0);
                t0b = __shfl_sync(0xffffffffu, u2, src1);
                t1b = __shfl_sync(0xffffffffu, u3, src1);
                unsigned a1 = odd ? t1  : t0;
                unsigned a3 = odd ? t1b : t0b;
                s[mi][ni][0] = __uint_as_float(a0);
                s[mi][ni][1] = __uint_as_float(a1);
                s[mi][ni][2] = __uint_as_float(a2);
                s[mi][ni][3] = __uint_as_float(a3);
            }
        }

        // ---- O += P V ----
#pragma unroll
        for (int nv = 0; nv < 4; nv++) {
#pragma unroll
            for (int kc = 0; kc < 8; kc++) {
                unsigned b[2];
                b[0] = f2tf(Vs[(kc*8 + q4    )*36 + nv*8 + gid]);
                b[1] = f2tf(Vs[(kc*8 + q4 + 4)*36 + nv*8 + gid]);
                const unsigned* pa0 = (const unsigned*)s[0][kc];
                const unsigned* pa1 = (const unsigned*)s[1][kc];
                mma_tf32(o[0][nv], pa0, b);
                mma_tf32(o[1][nv], pa1, b);
            }
        }
    }

    // ---- epilogue: finish row sums, normalize, write ----
    float inv[4];
#pragma unroll
    for (int idx = 0; idx < 4; idx++) {
        float l = lrow[idx];
        l += __shfl_xor_sync(0xffffffffu, l, 1);
        l += __shfl_xor_sync(0xffffffffu, l, 2);
        inv[idx] = 1.0f / l;
    }
#pragma unroll
    for (int mi = 0; mi < 2; mi++) {
#pragma unroll
        for (int rh = 0; rh < 2; rh++) {
            int row = qbase + mi*16 + rh*8 + gid;
            float iv = inv[mi*2 + rh];
#pragma unroll
            for (int nv = 0; nv < 4; nv++) {
                int col = h*32 + nv*8 + q4*2;
                float2 val;
                val.x = o[mi][nv][2*rh]   * iv;
                val.y = o[mi][nv][2*rh+1] * iv;
                *(float2*)(g_AO + ((size_t)n*LSEQ + row)*INNER + col) = val;
            }
        }
    }
}

// ---------------- FC GEMM + bias + residual: X = AO @ Wfc^T + bfc + q ------
__global__ __launch_bounds__(256) void fc_gemm(const float* __restrict__ Wfc,
                                               const float* __restrict__ bfc,
                                               const float* __restrict__ qres) {
    __shared__ float As[16][64];
    __shared__ float Ws[16][64];
    const int K = INNER;
    const int t = threadIdx.x;
    const int m0 = blockIdx.y * 64;
    const int n0 = blockIdx.x * 64;
    const int lrow = t >> 2;
    const int lk   = (t & 3) * 4;
    const int tx = t & 15, ty = t >> 4;

    float acc[4][4] = {};
    for (int k0 = 0; k0 < K; k0 += 16) {
        float4 av = *(const float4*)(g_AO + (size_t)(m0 + lrow) * K + k0 + lk);
        float4 wv = *(const float4*)(Wfc  + (size_t)(n0 + lrow) * K + k0 + lk);
        As[lk+0][lrow] = av.x; As[lk+1][lrow] = av.y;
        As[lk+2][lrow] = av.z; As[lk+3][lrow] = av.w;
        Ws[lk+0][lrow] = wv.x; Ws[lk+1][lrow] = wv.y;
        Ws[lk+2][lrow] = wv.z; Ws[lk+3][lrow] = wv.w;
        __syncthreads();
#pragma unroll
        for (int kk = 0; kk < 16; kk++) {
            float4 a = *(const float4*)&As[kk][ty*4];
            float4 b = *(const float4*)&Ws[kk][tx*4];
            float aa[4] = {a.x, a.y, a.z, a.w};
            float bb[4] = {b.x, b.y, b.z, b.w};
#pragma unroll
            for (int i = 0; i < 4; i++)
#pragma unroll
                for (int j = 0; j < 4; j++) acc[i][j] += aa[i] * bb[j];
        }
        __syncthreads();
    }
#pragma unroll
    for (int i = 0; i < 4; i++) {
        int m = m0 + ty*4 + i;
#pragma unroll
        for (int j = 0; j < 4; j++) {
            int c = n0 + tx*4 + j;
            float v = acc[i][j] + bfc[c] + qres[(size_t)m*DM + c];
            g_X[(size_t)m*DM + c] = v;
        }
    }
}

// ---------------- LayerNorm: one warp per 512-elem row ---------------------
__global__ __launch_bounds__(256) void ln_kernel(const float* __restrict__ gamma,
                                                 const float* __restrict__ beta,
                                                 float* __restrict__ out) {
    const int gw = (blockIdx.x * blockDim.x + threadIdx.x) >> 5;
    const int lane = threadIdx.x & 31;
    if (gw >= MROWS) return;

    const float4* xp = (const float4*)(g_X + (size_t)gw * DM);
    float4 v[4];
#pragma unroll
    for (int i = 0; i < 4; i++) v[i] = xp[lane + 32*i];

    float sum = 0.f;
#pragma unroll
    for (int i = 0; i < 4; i++) sum += v[i].x + v[i].y + v[i].z + v[i].w;
#pragma unroll
    for (int o = 16; o; o >>= 1) sum += __shfl_xor_sync(0xffffffffu, sum, o);
    const float mean = sum * (1.0f / DM);

    float sq = 0.f;
#pragma unroll
    for (int i = 0; i < 4; i++) {
        float dx = v[i].x - mean, dy = v[i].y - mean;
        float dz = v[i].z - mean, dw = v[i].w - mean;
        sq += dx*dx + dy*dy + dz*dz + dw*dw;
    }
#pragma unroll
    for (int o = 16; o; o >>= 1) sq += __shfl_xor_sync(0xffffffffu, sq, o);
    const float rstd = rsqrtf(sq * (1.0f / DM) + 1e-5f);

    const float4* gp = (const float4*)gamma;
    const float4* bp = (const float4*)beta;
    float4* op = (float4*)(out + (size_t)gw * DM);
#pragma unroll
    for (int i = 0; i < 4; i++) {
        float4 g = gp[lane + 32*i];
        float4 b = bp[lane + 32*i];
        float4 r;
        r.x = (v[i].x - mean) * rstd * g.x + b.x;
        r.y = (v[i].y - mean) * rstd * g.y + b.y;
        r.z = (v[i].z - mean) * rstd * g.z + b.z;
        r.w = (v[i].w - mean) * rstd * g.w + b.w;
        op[lane + 32*i] = r;
    }
}

// ---------------- launch ---------------------------------------------------
extern "C" void kernel_launch(void* const* d_in, const int* in_sizes, int n_in,
                              void* d_out, int out_size) {
    const float* q     = (const float*)d_in[0];
    const float* k     = (const float*)d_in[1];
    const float* v     = (const float*)d_in[2];
    const float* Wq    = (const float*)d_in[3];
    const float* bq    = (const float*)d_in[4];
    const float* Wk    = (const float*)d_in[5];
    const float* bk    = (const float*)d_in[6];
    const float* Wv    = (const float*)d_in[7];
    const float* bv    = (const float*)d_in[8];
    const float* Wfc   = (const float*)d_in[9];
    const float* bfc   = (const float*)d_in[10];
    const float* gamma = (const float*)d_in[11];
    const float* beta  = (const float*)d_in[12];

    dim3 gp(INNER/64, MROWS/64);          // (4, 128)
    proj_gemm<<<gp, 256>>>(q, Wq, bq, 0);
    proj_gemm<<<gp, 256>>>(k, Wk, bk, 1);
    proj_gemm<<<gp, 256>>>(v, Wv, bv, 2);

    dim3 ga(LSEQ/128, HN, BSZ);           // (16, 8, 4)
    attn_mma<<<ga, 128>>>();

    dim3 gf(DM/64, MROWS/64);             // (8, 128)
    fc_gemm<<<gf, 256>>>(Wfc, bfc, q);

    ln_kernel<<<MROWS/8, 256>>>(gamma, beta, (float*)d_out);
}

// round 3
// speedup vs baseline: 2.6096x; 1.4947x over previous
#include <cuda_runtime.h>
#include <math.h>

#define DM   512
#define HN   8
#define DKH  32
#define BSZ  4
#define LSEQ 2048
#define INNER 256            // HN*DKH
#define MROWS (BSZ*LSEQ)     // 8192

// ---------------- scratch (device globals; no allocation allowed) ----------
__device__ float g_Qh[BSZ*HN*LSEQ*DKH];   // [n][h][l][d]
__device__ float g_Kh[BSZ*HN*LSEQ*DKH];
__device__ float g_Vh[BSZ*HN*LSEQ*DKH];
__device__ float g_AO[MROWS*INNER];       // merged attn out [m][h*32+d]
__device__ float g_X [MROWS*DM];          // fc + residual (LN input)

// ---------------- mma helpers ----------------------------------------------
__device__ __forceinline__ unsigned f2tf(float f) {
    unsigned u;
    asm("cvt.rna.tf32.f32 %0, %1;" : "=r"(u) : "f"(f));
    return u;
}
__device__ __forceinline__ float f2tff(float f) {
    return __uint_as_float(f2tf(f));
}

__device__ __forceinline__ void mma_tf32(float c[4], const unsigned a[4], const unsigned b[2]) {
    asm volatile(
        "mma.sync.aligned.m16n8k8.row.col.f32.tf32.tf32.f32 "
        "{%0,%1,%2,%3}, {%4,%5,%6,%7}, {%8,%9}, {%0,%1,%2,%3};"
        : "+f"(c[0]), "+f"(c[1]), "+f"(c[2]), "+f"(c[3])
        : "r"(a[0]), "r"(a[1]), "r"(a[2]), "r"(a[3]),
          "r"(b[0]), "r"(b[1]));
}

// interleaved column position within 8-col groups: pairs (j, j+4) adjacent
__device__ __forceinline__ int ipos(int col) {
    return (col & ~7) + 2*(col & 3) + ((col >> 2) & 1);
}

// ---------------- fused projection GEMM (tf32 mma) -------------------------
// C[M=8192, N=256] = X @ W^T + b, scattered head-major. blockIdx.z selects q/k/v.
// CTA tile 128x64, 256 threads (8 warps as 4Mx2N, each 32x32).
__global__ __launch_bounds__(256) void proj_mma(
        const float* __restrict__ xq, const float* __restrict__ xk, const float* __restrict__ xv,
        const float* __restrict__ Wq, const float* __restrict__ Wk, const float* __restrict__ Wv,
        const float* __restrict__ bq, const float* __restrict__ bk, const float* __restrict__ bv) {
    const int which = blockIdx.z;
    const float* X    = (which == 0) ? xq : (which == 1) ? xk : xv;
    const float* W    = (which == 0) ? Wq : (which == 1) ? Wk : Wv;
    const float* bias = (which == 0) ? bq : (which == 1) ? bk : bv;
    float* Out        = (which == 0) ? g_Qh : (which == 1) ? g_Kh : g_Vh;

    __shared__ float As[128*40];
    __shared__ float Bs[64*40];

    const int t = threadIdx.x;
    const int m0 = blockIdx.y * 128, n0 = blockIdx.x * 64;
    const int warp = t >> 5, lane = t & 31;
    const int gid = lane >> 2, q4 = lane & 3;
    const int wm = warp & 3, wn = warp >> 2;

    float4 aR[4]; float4 bR[2];
#pragma unroll
    for (int j = 0; j < 4; j++) {
        int i = t + j*256; int row = i >> 3, c4 = (i & 7)*4;
        aR[j] = *(const float4*)(X + (size_t)(m0 + row)*DM + c4);
    }
#pragma unroll
    for (int j = 0; j < 2; j++) {
        int i = t + j*256; int row = i >> 3, c4 = (i & 7)*4;
        bR[j] = *(const float4*)(W + (size_t)(n0 + row)*DM + c4);
    }

    float acc[2][4][4] = {};

    const int NIT = DM / 32;    // 16
    for (int it = 0; it < NIT; it++) {
        __syncthreads();
#pragma unroll
        for (int j = 0; j < 4; j++) {
            int i = t + j*256; int row = i >> 3, c4 = (i & 7)*4;
            float* p = As + row*40 + (c4 & 24) + ((c4 & 4) ? 1 : 0);
            p[0] = f2tff(aR[j].x); p[2] = f2tff(aR[j].y);
            p[4] = f2tff(aR[j].z); p[6] = f2tff(aR[j].w);
        }
#pragma unroll
        for (int j = 0; j < 2; j++) {
            int i = t + j*256; int row = i >> 3, c4 = (i & 7)*4;
            float* p = Bs + row*40 + (c4 & 24) + ((c4 & 4) ? 1 : 0);
            p[0] = f2tff(bR[j].x); p[2] = f2tff(bR[j].y);
            p[4] = f2tff(bR[j].z); p[6] = f2tff(bR[j].w);
        }
        __syncthreads();
        if (it + 1 < NIT) {
            int k0 = (it + 1) * 32;
#pragma unroll
            for (int j = 0; j < 4; j++) {
                int i = t + j*256; int row = i >> 3, c4 = (i & 7)*4;
                aR[j] = *(const float4*)(X + (size_t)(m0 + row)*DM + k0 + c4);
            }
#pragma unroll
            for (int j = 0; j < 2; j++) {
                int i = t + j*256; int row = i >> 3, c4 = (i & 7)*4;
                bR[j] = *(const float4*)(W + (size_t)(n0 + row)*DM + k0 + c4);
            }
        }
#pragma unroll
        for (int ks = 0; ks < 4; ks++) {
            unsigned a[2][4];
#pragma unroll
            for (int mi = 0; mi < 2; mi++) {
                int r = wm*32 + mi*16 + gid;
                float2 lo = *(const float2*)&As[r*40     + ks*8 + 2*q4];
                float2 hi = *(const float2*)&As[(r+8)*40 + ks*8 + 2*q4];
                a[mi][0] = __float_as_uint(lo.x);
                a[mi][1] = __float_as_uint(hi.x);
                a[mi][2] = __float_as_uint(lo.y);
                a[mi][3] = __float_as_uint(hi.y);
            }
#pragma unroll
            for (int ni = 0; ni < 4; ni++) {
                int rb = wn*32 + ni*8 + gid;
                float2 bb = *(const float2*)&Bs[rb*40 + ks*8 + 2*q4];
                unsigned b[2] = { __float_as_uint(bb.x), __float_as_uint(bb.y) };
                mma_tf32(acc[0][ni], a[0], b);
                mma_tf32(acc[1][ni], a[1], b);
            }
        }
    }

    // epilogue: scatter head-major  Out[n][h][l][d],  c = d*8 + h
#pragma unroll
    for (int mi = 0; mi < 2; mi++) {
#pragma unroll
        for (int ni = 0; ni < 4; ni++) {
            int r0 = m0 + wm*32 + mi*16 + gid;
            int c0 = n0 + wn*32 + ni*8 + 2*q4;
#pragma unroll
            for (int rr = 0; rr < 2; rr++) {
#pragma unroll
                for (int cc = 0; cc < 2; cc++) {
                    int m = r0 + rr*8, c = c0 + cc;
                    float v = acc[mi][ni][rr*2 + cc] + __ldg(bias + c);
                    int nb = m >> 11, l = m & 2047;
                    int d = c >> 3, hh = c & 7;
                    Out[((((size_t)nb*HN + hh)*LSEQ + l)*DKH) + d] = v;
                }
            }
        }
    }
}

// ---------------- flash attention (tf32 mma, 16 q/warp, 256 thr) -----------
__global__ __launch_bounds__(256) void attn_mma() {
    const int n = blockIdx.z, h = blockIdx.y;
    const int tid  = threadIdx.x;
    const int warp = tid >> 5, lane = tid & 31;
    const int gid  = lane >> 2, q4 = lane & 3;
    const int qbase = blockIdx.x * 128 + warp * 16;
    // scale * log2(e): softmax done in exp2 domain
    const float qscale = 0.17677669529663687f * 1.4426950408889634f;

    const size_t slab = (((size_t)n*HN + h) * LSEQ) * DKH;
    const float* Qg = g_Qh + slab;
    const float* Kg = g_Kh + slab;
    const float* Vg = g_Vh + slab;

    __shared__ float Ks[64*40];   // 64 keys x 32 d, col-interleaved, tf32 bits
    __shared__ float Vt[32*72];   // 32 d x 64 keys (transposed), key-interleaved

    // Q fragments (scale folded, tf32)
    unsigned qa[4][4];
    {
        int r0 = qbase + gid;
#pragma unroll
        for (int kk = 0; kk < 4; kk++) {
            int c0 = kk*8 + q4;
            qa[kk][0] = f2tf(Qg[(size_t)r0*32     + c0    ] * qscale);
            qa[kk][1] = f2tf(Qg[(size_t)(r0+8)*32 + c0    ] * qscale);
            qa[kk][2] = f2tf(Qg[(size_t)r0*32     + c0 + 4] * qscale);
            qa[kk][3] = f2tf(Qg[(size_t)(r0+8)*32 + c0 + 4] * qscale);
        }
    }

    float o[4][4] = {};
    float mrow[2] = {-1e30f, -1e30f};
    float lrow[2] = {0.f, 0.f};

    const int src0 = (lane & ~3) | (q4 >> 1);
    const int src1 = src0 + 2;
    const bool odd = (q4 & 1);

    for (int kt = 0; kt < LSEQ; kt += 64) {
        __syncthreads();
#pragma unroll
        for (int j = 0; j < 2; j++) {
            int i = tid + j*256;
            int row = i >> 3, c4 = (i & 7)*4;       // key row, d col base
            float4 kv = *(const float4*)(Kg + (size_t)(kt + row)*32 + c4);
            float4 vv = *(const float4*)(Vg + (size_t)(kt + row)*32 + c4);
            float* kp = Ks + row*40 + (c4 & 24) + ((c4 & 4) ? 1 : 0);
            kp[0] = f2tff(kv.x); kp[2] = f2tff(kv.y);
            kp[4] = f2tff(kv.z); kp[6] = f2tff(kv.w);
            int pk = (row & ~7) + 2*(row & 3) + ((row >> 2) & 1);
            Vt[(c4+0)*72 + pk] = f2tff(vv.x);
            Vt[(c4+1)*72 + pk] = f2tff(vv.y);
            Vt[(c4+2)*72 + pk] = f2tff(vv.z);
            Vt[(c4+3)*72 + pk] = f2tff(vv.w);
        }
        __syncthreads();

        // ---- S = Q K^T (log2 domain) ----
        float s[8][4] = {};
#pragma unroll
        for (int ni = 0; ni < 8; ni++) {
            int krow = ni*8 + gid;
#pragma unroll
            for (int kk = 0; kk < 4; kk++) {
                float2 bb = *(const float2*)&Ks[krow*40 + kk*8 + 2*q4];
                unsigned b[2] = { __float_as_uint(bb.x), __float_as_uint(bb.y) };
                mma_tf32(s[ni], qa[kk], b);
            }
        }

        // ---- online softmax (exp2) ----
#pragma unroll
        for (int rh = 0; rh < 2; rh++) {
            float tmax = -1e30f;
#pragma unroll
            for (int ni = 0; ni < 8; ni++)
                tmax = fmaxf(tmax, fmaxf(s[ni][2*rh], s[ni][2*rh+1]));
            tmax = fmaxf(tmax, __shfl_xor_sync(0xffffffffu, tmax, 1));
            tmax = fmaxf(tmax, __shfl_xor_sync(0xffffffffu, tmax, 2));
            float mnew = fmaxf(mrow[rh], tmax);
            float corr = exp2f(mrow[rh] - mnew);
            mrow[rh] = mnew;
            float lsum = lrow[rh] * corr;
#pragma unroll
            for (int nv = 0; nv < 4; nv++) {
                o[nv][2*rh]   *= corr;
                o[nv][2*rh+1] *= corr;
            }
#pragma unroll
            for (int ni = 0; ni < 8; ni++) {
                float p0 = exp2f(s[ni][2*rh]   - mnew);
                float p1 = exp2f(s[ni][2*rh+1] - mnew);
                lsum += p0 + p1;
                s[ni][2*rh]   = p0;
                s[ni][2*rh+1] = p1;
            }
            lrow[rh] = lsum;
        }

        // ---- permute P: accumulator layout -> A-operand layout (tf32) ----
#pragma unroll
        for (int ni = 0; ni < 8; ni++) {
            unsigned u0 = f2tf(s[ni][0]);
            unsigned u1 = f2tf(s[ni][1]);
            unsigned u2 = f2tf(s[ni][2]);
            unsigned u3 = f2tf(s[ni][3]);
            unsigned t0  = __shfl_sync(0xffffffffu, u0, src0);
            unsigned t1  = __shfl_sync(0xffffffffu, u1, src0);
            unsigned t0b = __shfl_sync(0xffffffffu, u0, src1);
            unsigned t1b = __shfl_sync(0xffffffffu, u1, src1);
            unsigned a0 = odd ? t1  : t0;
            unsigned a2 = odd ? t1b : t0b;
            t0  = __shfl_sync(0xffffffffu, u2, src0);
            t1  = __shfl_sync(0xffffffffu, u3, src0);
            t0b = __shfl_sync(0xffffffffu, u2, src1);
            t1b = __shfl_sync(0xffffffffu, u3, src1);
            unsigned a1 = odd ? t1  : t0;
            unsigned a3 = odd ? t1b : t0b;
            s[ni][0] = __uint_as_float(a0);
            s[ni][1] = __uint_as_float(a1);
            s[ni][2] = __uint_as_float(a2);
            s[ni][3] = __uint_as_float(a3);
        }

        // ---- O += P V ----
#pragma unroll
        for (int nv = 0; nv < 4; nv++) {
#pragma unroll
            for (int kc = 0; kc < 8; kc++) {
                float2 bb = *(const float2*)&Vt[(nv*8 + gid)*72 + kc*8 + 2*q4];
                unsigned b[2] = { __float_as_uint(bb.x), __float_as_uint(bb.y) };
                mma_tf32(o[nv], (const unsigned*)s[kc], b);
            }
        }
    }

    // ---- epilogue ----
    float inv[2];
#pragma unroll
    for (int rh = 0; rh < 2; rh++) {
        float l = lrow[rh];
        l += __shfl_xor_sync(0xffffffffu, l, 1);
        l += __shfl_xor_sync(0xffffffffu, l, 2);
        inv[rh] = 1.0f / l;
    }
#pragma unroll
    for (int rh = 0; rh < 2; rh++) {
        int row = qbase + rh*8 + gid;
        float iv = inv[rh];
#pragma unroll
        for (int nv = 0; nv < 4; nv++) {
            int col = h*32 + nv*8 + q4*2;
            float2 val;
            val.x = o[nv][2*rh]   * iv;
            val.y = o[nv][2*rh+1] * iv;
            *(float2*)(g_AO + ((size_t)n*LSEQ + row)*INNER + col) = val;
        }
    }
}

// ---------------- FC GEMM (tf32 mma) + bias + residual ---------------------
// X[M=8192, N=512] = AO[M,256] @ Wfc^T + bfc + q
__global__ __launch_bounds__(256) void fc_mma(const float* __restrict__ Wfc,
                                              const float* __restrict__ bfc,
                                              const float* __restrict__ qres) {
    __shared__ float As[128*40];
    __shared__ float Bs[64*40];

    const int t = threadIdx.x;
    const int m0 = blockIdx.y * 128, n0 = blockIdx.x * 64;
    const int warp = t >> 5, lane = t & 31;
    const int gid = lane >> 2, q4 = lane & 3;
    const int wm = warp & 3, wn = warp >> 2;

    float4 aR[4]; float4 bR[2];
#pragma unroll
    for (int j = 0; j < 4; j++) {
        int i = t + j*256; int row = i >> 3, c4 = (i & 7)*4;
        aR[j] = *(const float4*)(g_AO + (size_t)(m0 + row)*INNER + c4);
    }
#pragma unroll
    for (int j = 0; j < 2; j++) {
        int i = t + j*256; int row = i >> 3, c4 = (i & 7)*4;
        bR[j] = *(const float4*)(Wfc + (size_t)(n0 + row)*INNER + c4);
    }

    float acc[2][4][4] = {};
    const int NIT = INNER / 32;   // 8
    for (int it = 0; it < NIT; it++) {
        __syncthreads();
#pragma unroll
        for (int j = 0; j < 4; j++) {
            int i = t + j*256; int row = i >> 3, c4 = (i & 7)*4;
            float* p = As + row*40 + (c4 & 24) + ((c4 & 4) ? 1 : 0);
            p[0] = f2tff(aR[j].x); p[2] = f2tff(aR[j].y);
            p[4] = f2tff(aR[j].z); p[6] = f2tff(aR[j].w);
        }
#pragma unroll
        for (int j = 0; j < 2; j++) {
            int i = t + j*256; int row = i >> 3, c4 = (i & 7)*4;
            float* p = Bs + row*40 + (c4 & 24) + ((c4 & 4) ? 1 : 0);
            p[0] = f2tff(bR[j].x); p[2] = f2tff(bR[j].y);
            p[4] = f2tff(bR[j].z); p[6] = f2tff(bR[j].w);
        }
        __syncthreads();
        if (it + 1 < NIT) {
            int k0 = (it + 1) * 32;
#pragma unroll
            for (int j = 0; j < 4; j++) {
                int i = t + j*256; int row = i >> 3, c4 = (i & 7)*4;
                aR[j] = *(const float4*)(g_AO + (size_t)(m0 + row)*INNER + k0 + c4);
            }
#pragma unroll
            for (int j = 0; j < 2; j++) {
                int i = t + j*256; int row = i >> 3, c4 = (i & 7)*4;
                bR[j] = *(const float4*)(Wfc + (size_t)(n0 + row)*INNER + k0 + c4);
            }
        }
#pragma unroll
        for (int ks = 0; ks < 4; ks++) {
            unsigned a[2][4];
#pragma unroll
            for (int mi = 0; mi < 2; mi++) {
                int r = wm*32 + mi*16 + gid;
                float2 lo = *(const float2*)&As[r*40     + ks*8 + 2*q4];
                float2 hi = *(const float2*)&As[(r+8)*40 + ks*8 + 2*q4];
                a[mi][0] = __float_as_uint(lo.x);
                a[mi][1] = __float_as_uint(hi.x);
                a[mi][2] = __float_as_uint(lo.y);
                a[mi][3] = __float_as_uint(hi.y);
            }
#pragma unroll
            for (int ni = 0; ni < 4; ni++) {
                int rb = wn*32 + ni*8 + gid;
                float2 bb = *(const float2*)&Bs[rb*40 + ks*8 + 2*q4];
                unsigned b[2] = { __float_as_uint(bb.x), __float_as_uint(bb.y) };
                mma_tf32(acc[0][ni], a[0], b);
                mma_tf32(acc[1][ni], a[1], b);
            }
        }
    }

    // epilogue: + bias + residual, contiguous float2 stores
#pragma unroll
    for (int mi = 0; mi < 2; mi++) {
#pragma unroll
        for (int ni = 0; ni < 4; ni++) {
            int c0 = n0 + wn*32 + ni*8 + 2*q4;
            float2 bias2 = *(const float2*)(bfc + c0);
#pragma unroll
            for (int rr = 0; rr < 2; rr++) {
                int m = m0 + wm*32 + mi*16 + gid + rr*8;
                float2 res = *(const float2*)(qres + (size_t)m*DM + c0);
                float2 v;
                v.x = acc[mi][ni][rr*2 + 0] + bias2.x + res.x;
                v.y = acc[mi][ni][rr*2 + 1] + bias2.y + res.y;
                *(float2*)(g_X + (size_t)m*DM + c0) = v;
            }
        }
    }
}

// ---------------- LayerNorm: one warp per 512-elem row ---------------------
__global__ __launch_bounds__(256) void ln_kernel(const float* __restrict__ gamma,
                                                 const float* __restrict__ beta,
                                                 float* __restrict__ out) {
    const int gw = (blockIdx.x * blockDim.x + threadIdx.x) >> 5;
    const int lane = threadIdx.x & 31;
    if (gw >= MROWS) return;

    const float4* xp = (const float4*)(g_X + (size_t)gw * DM);
    float4 v[4];
#pragma unroll
    for (int i = 0; i < 4; i++) v[i] = xp[lane + 32*i];

    float sum = 0.f;
#pragma unroll
    for (int i = 0; i < 4; i++) sum += v[i].x + v[i].y + v[i].z + v[i].w;
#pragma unroll
    for (int o = 16; o; o >>= 1) sum += __shfl_xor_sync(0xffffffffu, sum, o);
    const float mean = sum * (1.0f / DM);

    float sq = 0.f;
#pragma unroll
    for (int i = 0; i < 4; i++) {
        float dx = v[i].x - mean, dy = v[i].y - mean;
        float dz = v[i].z - mean, dw = v[i].w - mean;
        sq += dx*dx + dy*dy + dz*dz + dw*dw;
    }
#pragma unroll
    for (int o = 16; o; o >>= 1) sq += __shfl_xor_sync(0xffffffffu, sq, o);
    const float rstd = rsqrtf(sq * (1.0f / DM) + 1e-5f);

    const float4* gp = (const float4*)gamma;
    const float4* bp = (const float4*)beta;
    float4* op = (float4*)(out + (size_t)gw * DM);
#pragma unroll
    for (int i = 0; i < 4; i++) {
        float4 g = gp[lane + 32*i];
        float4 b = bp[lane + 32*i];
        float4 r;
        r.x = (v[i].x - mean) * rstd * g.x + b.x;
        r.y = (v[i].y - mean) * rstd * g.y + b.y;
        r.z = (v[i].z - mean) * rstd * g.z + b.z;
        r.w = (v[i].w - mean) * rstd * g.w + b.w;
        op[lane + 32*i] = r;
    }
}

// ---------------- launch ---------------------------------------------------
extern "C" void kernel_launch(void* const* d_in, const int* in_sizes, int n_in,
                              void* d_out, int out_size) {
    const float* q     = (const float*)d_in[0];
    const float* k     = (const float*)d_in[1];
    const float* v     = (const float*)d_in[2];
    const float* Wq    = (const float*)d_in[3];
    const float* bq    = (const float*)d_in[4];
    const float* Wk    = (const float*)d_in[5];
    const float* bk    = (const float*)d_in[6];
    const float* Wv    = (const float*)d_in[7];
    const float* bv    = (const float*)d_in[8];
    const float* Wfc   = (const float*)d_in[9];
    const float* bfc   = (const float*)d_in[10];
    const float* gamma = (const float*)d_in[11];
    const float* beta  = (const float*)d_in[12];

    dim3 gp(INNER/64, MROWS/128, 3);      // (4, 64, 3)
    proj_mma<<<gp, 256>>>(q, k, v, Wq, Wk, Wv, bq, bk, bv);

    dim3 ga(LSEQ/128, HN, BSZ);           // (16, 8, 4)
    attn_mma<<<ga, 256>>>();

    dim3 gf(DM/64, MROWS/128);            // (8, 64)
    fc_mma<<<gf, 256>>>(Wfc, bfc, q);

    ln_kernel<<<MROWS/8, 256>>>(gamma, beta, (float*)d_out);
}

// round 4
// speedup vs baseline: 3.5131x; 1.3462x over previous
#include <cuda_runtime.h>
#include <cuda_fp16.h>
#include <math.h>

#define DM   512
#define HN   8
#define DKH  32
#define BSZ  4
#define LSEQ 2048
#define INNER 256            // HN*DKH
#define MROWS (BSZ*LSEQ)     // 8192

// Q pre-scale: 1/sqrt(32) * log2(e)  (softmax runs in exp2 domain)
#define QSCALE (0.17677669529663687f * 1.4426950408889634f)

// ---------------- scratch (device globals; no allocation allowed) ----------
__device__ __half g_Qh[BSZ*HN*LSEQ*DKH];  // [n][h][l][d], pre-scaled, fp16
__device__ __half g_Kh[BSZ*HN*LSEQ*DKH];  // fp16
__device__ __half g_Vh[BSZ*HN*LSEQ*DKH];  // fp16
__device__ float  g_AO[MROWS*INNER];      // attn out [m][h*32+d], fp32
__device__ float  g_X [MROWS*DM];         // fc + residual (LN input)

// ---------------- helpers ----------------------------------------------
__device__ __forceinline__ unsigned f2tf(float f) {
    unsigned u;
    asm("cvt.rna.tf32.f32 %0, %1;" : "=r"(u) : "f"(f));
    return u;
}
__device__ __forceinline__ float f2tff(float f) {
    return __uint_as_float(f2tf(f));
}
__device__ __forceinline__ float ex2(float x) {
    float r;
    asm("ex2.approx.f32 %0, %1;" : "=f"(r) : "f"(x));
    return r;
}
__device__ __forceinline__ unsigned pack_h2(float lo, float hi) {
    __half2 h = __floats2half2_rn(lo, hi);      // x = lo, y = hi
    return *(unsigned*)&h;
}

__device__ __forceinline__ void mma_tf32(float c[4], const unsigned a[4], const unsigned b[2]) {
    asm volatile(
        "mma.sync.aligned.m16n8k8.row.col.f32.tf32.tf32.f32 "
        "{%0,%1,%2,%3}, {%4,%5,%6,%7}, {%8,%9}, {%0,%1,%2,%3};"
        : "+f"(c[0]), "+f"(c[1]), "+f"(c[2]), "+f"(c[3])
        : "r"(a[0]), "r"(a[1]), "r"(a[2]), "r"(a[3]),
          "r"(b[0]), "r"(b[1]));
}

__device__ __forceinline__ void mma_f16(float c[4], const unsigned a[4],
                                        unsigned b0, unsigned b1) {
    asm volatile(
        "mma.sync.aligned.m16n8k16.row.col.f32.f16.f16.f32 "
        "{%0,%1,%2,%3}, {%4,%5,%6,%7}, {%8,%9}, {%0,%1,%2,%3};"
        : "+f"(c[0]), "+f"(c[1]), "+f"(c[2]), "+f"(c[3])
        : "r"(a[0]), "r"(a[1]), "r"(a[2]), "r"(a[3]),
          "r"(b0), "r"(b1));
}

// ---------------- fused projection GEMM (tf32 mma) -------------------------
// C[M=8192, N=256] = X @ W^T + b, scattered head-major as fp16.
// CTA tile 128x64, 256 threads (8 warps: 4M x 2N, each 32x32).
__global__ __launch_bounds__(256) void proj_mma(
        const float* __restrict__ xq, const float* __restrict__ xk, const float* __restrict__ xv,
        const float* __restrict__ Wq, const float* __restrict__ Wk, const float* __restrict__ Wv,
        const float* __restrict__ bq, const float* __restrict__ bk, const float* __restrict__ bv) {
    const int which = blockIdx.z;
    const float* X    = (which == 0) ? xq : (which == 1) ? xk : xv;
    const float* W    = (which == 0) ? Wq : (which == 1) ? Wk : Wv;
    const float* bias = (which == 0) ? bq : (which == 1) ? bk : bv;
    __half* Out       = (which == 0) ? g_Qh : (which == 1) ? g_Kh : g_Vh;
    const float oscale = (which == 0) ? QSCALE : 1.0f;

    __shared__ float As[128*40];
    __shared__ float Bs[64*40];

    const int t = threadIdx.x;
    const int m0 = blockIdx.y * 128, n0 = blockIdx.x * 64;
    const int warp = t >> 5, lane = t & 31;
    const int gid = lane >> 2, q4 = lane & 3;
    const int wm = warp & 3, wn = warp >> 2;

    float4 aR[4]; float4 bR[2];
#pragma unroll
    for (int j = 0; j < 4; j++) {
        int i = t + j*256; int row = i >> 3, c4 = (i & 7)*4;
        aR[j] = *(const float4*)(X + (size_t)(m0 + row)*DM + c4);
    }
#pragma unroll
    for (int j = 0; j < 2; j++) {
        int i = t + j*256; int row = i >> 3, c4 = (i & 7)*4;
        bR[j] = *(const float4*)(W + (size_t)(n0 + row)*DM + c4);
    }

    float acc[2][4][4] = {};

    const int NIT = DM / 32;    // 16
    for (int it = 0; it < NIT; it++) {
        __syncthreads();
#pragma unroll
        for (int j = 0; j < 4; j++) {
            int i = t + j*256; int row = i >> 3, c4 = (i & 7)*4;
            float* p = As + row*40 + (c4 & 24) + ((c4 & 4) ? 1 : 0);
            p[0] = f2tff(aR[j].x); p[2] = f2tff(aR[j].y);
            p[4] = f2tff(aR[j].z); p[6] = f2tff(aR[j].w);
        }
#pragma unroll
        for (int j = 0; j < 2; j++) {
            int i = t + j*256; int row = i >> 3, c4 = (i & 7)*4;
            float* p = Bs + row*40 + (c4 & 24) + ((c4 & 4) ? 1 : 0);
            p[0] = f2tff(bR[j].x); p[2] = f2tff(bR[j].y);
            p[4] = f2tff(bR[j].z); p[6] = f2tff(bR[j].w);
        }
        __syncthreads();
        if (it + 1 < NIT) {
            int k0 = (it + 1) * 32;
#pragma unroll
            for (int j = 0; j < 4; j++) {
                int i = t + j*256; int row = i >> 3, c4 = (i & 7)*4;
                aR[j] = *(const float4*)(X + (size_t)(m0 + row)*DM + k0 + c4);
            }
#pragma unroll
            for (int j = 0; j < 2; j++) {
                int i = t + j*256; int row = i >> 3, c4 = (i & 7)*4;
                bR[j] = *(const float4*)(W + (size_t)(n0 + row)*DM + k0 + c4);
            }
        }
#pragma unroll
        for (int ks = 0; ks < 4; ks++) {
            unsigned a[2][4];
#pragma unroll
            for (int mi = 0; mi < 2; mi++) {
                int r = wm*32 + mi*16 + gid;
                float2 lo = *(const float2*)&As[r*40     + ks*8 + 2*q4];
                float2 hi = *(const float2*)&As[(r+8)*40 + ks*8 + 2*q4];
                a[mi][0] = __float_as_uint(lo.x);
                a[mi][1] = __float_as_uint(hi.x);
                a[mi][2] = __float_as_uint(lo.y);
                a[mi][3] = __float_as_uint(hi.y);
            }
#pragma unroll
            for (int ni = 0; ni < 4; ni++) {
                int rb = wn*32 + ni*8 + gid;
                float2 bb = *(const float2*)&Bs[rb*40 + ks*8 + 2*q4];
                unsigned b[2] = { __float_as_uint(bb.x), __float_as_uint(bb.y) };
                mma_tf32(acc[0][ni], a[0], b);
                mma_tf32(acc[1][ni], a[1], b);
            }
        }
    }

    // epilogue: scatter head-major fp16  Out[n][h][l][d],  c = d*8 + h
#pragma unroll
    for (int mi = 0; mi < 2; mi++) {
#pragma unroll
        for (int ni = 0; ni < 4; ni++) {
            int r0 = m0 + wm*32 + mi*16 + gid;
            int c0 = n0 + wn*32 + ni*8 + 2*q4;
#pragma unroll
            for (int rr = 0; rr < 2; rr++) {
#pragma unroll
                for (int cc = 0; cc < 2; cc++) {
                    int m = r0 + rr*8, c = c0 + cc;
                    float v = (acc[mi][ni][rr*2 + cc] + __ldg(bias + c)) * oscale;
                    int nb = m >> 11, l = m & 2047;
                    int d = c >> 3, hh = c & 7;
                    Out[((((size_t)nb*HN + hh)*LSEQ + l)*DKH) + d] = __float2half_rn(v);
                }
            }
        }
    }
}

// ---------------- flash attention (fp16 mma, fp32 acc, zero-shuffle P) -----
// CTA = one (n,h), 128 queries; 8 warps x 16 queries. 64-key tiles.
__global__ __launch_bounds__(256) void attn_f16() {
    const int n = blockIdx.z, h = blockIdx.y;
    const int tid  = threadIdx.x;
    const int warp = tid >> 5, lane = tid & 31;
    const int gid  = lane >> 2, q4 = lane & 3;
    const int qbase = blockIdx.x * 128 + warp * 16;

    const size_t slab = (((size_t)n*HN + h) * LSEQ) * DKH;
    const __half* Qg = g_Qh + slab;
    const __half* Kg = g_Kh + slab;
    const __half* Vg = g_Vh + slab;

    // Ksm: [64 keys][16 words of half2 (d pairs), interleaved, stride 24]
    // Vsm: [32 d][32 words of half2 (key pairs), interleaved, stride 40]
    __shared__ unsigned Ksm[64*24];
    __shared__ unsigned Vsm[32*40];

    // ---- Q fragments (already scaled + fp16 in gmem) ----
    unsigned qa[2][4];
    {
        const __half* qp  = Qg + (size_t)(qbase + gid) * 32;
        const __half* qp8 = qp + 8*32;
#pragma unroll
        for (int kk = 0; kk < 2; kk++) {
            qa[kk][0] = *(const unsigned*)(qp  + kk*16 + 2*q4);
            qa[kk][1] = *(const unsigned*)(qp8 + kk*16 + 2*q4);
            qa[kk][2] = *(const unsigned*)(qp  + kk*16 + 2*q4 + 8);
            qa[kk][3] = *(const unsigned*)(qp8 + kk*16 + 2*q4 + 8);
        }
    }

    float o[4][4] = {};
    float mrow[2] = {-1e30f, -1e30f};
    float lrow[2] = {0.f, 0.f};

    // staging thread mapping
    const int kKey = tid >> 2;              // K: key row (0..63)
    const int kW   = (tid & 3) * 4;         // K: first of 4 words
    const int vKp  = tid & 31;              // V: key pair (0..31)
    const int vD   = (tid >> 5) * 4;        // V: d base (0..28)
    const int vpos = (vKp & 24) + 2*(vKp & 3) + ((vKp >> 2) & 1);

    // preload tile 0 into regs
    uint4 kR = ((const uint4*)Kg)[tid];
    uint2 vA = *(const uint2*)(Vg + (size_t)(2*vKp    )*32 + vD);
    uint2 vB = *(const uint2*)(Vg + (size_t)(2*vKp + 1)*32 + vD);

    for (int kt = 0; kt < LSEQ; kt += 64) {
        __syncthreads();
        {   // store staged regs -> smem (interleaved layouts)
            unsigned kv[4] = {kR.x, kR.y, kR.z, kR.w};
#pragma unroll
            for (int c = 0; c < 4; c++) {
                int w = kW + c;
                int p = (w & 8) + 2*(w & 3) + ((w >> 2) & 1);
                Ksm[kKey*24 + p] = kv[c];
            }
            Vsm[(vD+0)*40 + vpos] = __byte_perm(vA.x, vB.x, 0x5410);
            Vsm[(vD+1)*40 + vpos] = __byte_perm(vA.x, vB.x, 0x7632);
            Vsm[(vD+2)*40 + vpos] = __byte_perm(vA.y, vB.y, 0x5410);
            Vsm[(vD+3)*40 + vpos] = __byte_perm(vA.y, vB.y, 0x7632);
        }
        __syncthreads();
        if (kt + 64 < LSEQ) {   // prefetch next tile
            kR = ((const uint4*)(Kg + (size_t)(kt + 64)*32))[tid];
            vA = *(const uint2*)(Vg + (size_t)(kt + 64 + 2*vKp    )*32 + vD);
            vB = *(const uint2*)(Vg + (size_t)(kt + 64 + 2*vKp + 1)*32 + vD);
        }

        // ---- S = Q K^T (log2 domain; scale folded into Q) ----
        float s[8][4] = {};
#pragma unroll
        for (int ni = 0; ni < 8; ni++) {
            const unsigned* kr = &Ksm[(ni*8 + gid)*24 + 2*q4];
#pragma unroll
            for (int kk = 0; kk < 2; kk++) {
                uint2 b = *(const uint2*)(kr + kk*8);
                mma_f16(s[ni], qa[kk], b.x, b.y);
            }
        }

        // ---- online softmax (exp2) ----
#pragma unroll
        for (int rh = 0; rh < 2; rh++) {
            float tmax = -1e30f;
#pragma unroll
            for (int ni = 0; ni < 8; ni++)
                tmax = fmaxf(tmax, fmaxf(s[ni][2*rh], s[ni][2*rh+1]));
            tmax = fmaxf(tmax, __shfl_xor_sync(0xffffffffu, tmax, 1));
            tmax = fmaxf(tmax, __shfl_xor_sync(0xffffffffu, tmax, 2));
            float mnew = fmaxf(mrow[rh], tmax);
            float corr = ex2(mrow[rh] - mnew);
            mrow[rh] = mnew;
            float lsum = lrow[rh] * corr;
#pragma unroll
            for (int nv = 0; nv < 4; nv++) {
                o[nv][2*rh]   *= corr;
                o[nv][2*rh+1] *= corr;
            }
#pragma unroll
            for (int ni = 0; ni < 8; ni++) {
                float p0 = ex2(s[ni][2*rh]   - mnew);
                float p1 = ex2(s[ni][2*rh+1] - mnew);
                lsum += p0 + p1;
                s[ni][2*rh]   = p0;
                s[ni][2*rh+1] = p1;
            }
            lrow[rh] = lsum;
        }

        // ---- O += P V : accumulator layout == A layout for f16 (pack only) ----
#pragma unroll
        for (int kc = 0; kc < 4; kc++) {
            unsigned pa[4];
            pa[0] = pack_h2(s[2*kc  ][0], s[2*kc  ][1]);
            pa[1] = pack_h2(s[2*kc  ][2], s[2*kc  ][3]);
            pa[2] = pack_h2(s[2*kc+1][0], s[2*kc+1][1]);
            pa[3] = pack_h2(s[2*kc+1][2], s[2*kc+1][3]);
#pragma unroll
            for (int nv = 0; nv < 4; nv++) {
                uint2 b = *(const uint2*)&Vsm[(nv*8 + gid)*40 + kc*8 + 2*q4];
                mma_f16(o[nv], pa, b.x, b.y);
            }
        }
    }

    // ---- epilogue: finish row sums, normalize, write fp32 ----
    float inv[2];
#pragma unroll
    for (int rh = 0; rh < 2; rh++) {
        float l = lrow[rh];
        l += __shfl_xor_sync(0xffffffffu, l, 1);
        l += __shfl_xor_sync(0xffffffffu, l, 2);
        inv[rh] = 1.0f / l;
    }
#pragma unroll
    for (int rh = 0; rh < 2; rh++) {
        int row = qbase + rh*8 + gid;
        float iv = inv[rh];
#pragma unroll
        for (int nv = 0; nv < 4; nv++) {
            int col = h*32 + nv*8 + q4*2;
            float2 val;
            val.x = o[nv][2*rh]   * iv;
            val.y = o[nv][2*rh+1] * iv;
            *(float2*)(g_AO + ((size_t)n*LSEQ + row)*INNER + col) = val;
        }
    }
}

// ---------------- FC GEMM (tf32 mma) + bias + residual ---------------------
// X[M=8192, N=512] = AO[M,256] @ Wfc^T + bfc + q
__global__ __launch_bounds__(256) void fc_mma(const float* __restrict__ Wfc,
                                              const float* __restrict__ bfc,
                                              const float* __restrict__ qres) {
    __shared__ float As[128*40];
    __shared__ float Bs[64*40];

    const int t = threadIdx.x;
    const int m0 = blockIdx.y * 128, n0 = blockIdx.x * 64;
    const int warp = t >> 5, lane = t & 31;
    const int gid = lane >> 2, q4 = lane & 3;
    const int wm = warp & 3, wn = warp >> 2;

    float4 aR[4]; float4 bR[2];
#pragma unroll
    for (int j = 0; j < 4; j++) {
        int i = t + j*256; int row = i >> 3, c4 = (i & 7)*4;
        aR[j] = *(const float4*)(g_AO + (size_t)(m0 + row)*INNER + c4);
    }
#pragma unroll
    for (int j = 0; j < 2; j++) {
        int i = t + j*256; int row = i >> 3, c4 = (i & 7)*4;
        bR[j] = *(const float4*)(Wfc + (size_t)(n0 + row)*INNER + c4);
    }

    float acc[2][4][4] = {};
    const int NIT = INNER / 32;   // 8
    for (int it = 0; it < NIT; it++) {
        __syncthreads();
#pragma unroll
        for (int j = 0; j < 4; j++) {
            int i = t + j*256; int row = i >> 3, c4 = (i & 7)*4;
            float* p = As + row*40 + (c4 & 24) + ((c4 & 4) ? 1 : 0);
            p[0] = f2tff(aR[j].x); p[2] = f2tff(aR[j].y);
            p[4] = f2tff(aR[j].z); p[6] = f2tff(aR[j].w);
        }
#pragma unroll
        for (int j = 0; j < 2; j++) {
            int i = t + j*256; int row = i >> 3, c4 = (i & 7)*4;
            float* p = Bs + row*40 + (c4 & 24) + ((c4 & 4) ? 1 : 0);
            p[0] = f2tff(bR[j].x); p[2] = f2tff(bR[j].y);
            p[4] = f2tff(bR[j].z); p[6] = f2tff(bR[j].w);
        }
        __syncthreads();
        if (it + 1 < NIT) {
            int k0 = (it + 1) * 32;
#pragma unroll
            for (int j = 0; j < 4; j++) {
                int i = t + j*256; int row = i >> 3, c4 = (i & 7)*4;
                aR[j] = *(const float4*)(g_AO + (size_t)(m0 + row)*INNER + k0 + c4);
            }
#pragma unroll
            for (int j = 0; j < 2; j++) {
                int i = t + j*256; int row = i >> 3, c4 = (i & 7)*4;
                bR[j] = *(const float4*)(Wfc + (size_t)(n0 + row)*INNER + k0 + c4);
            }
        }
#pragma unroll
        for (int ks = 0; ks < 4; ks++) {
            unsigned a[2][4];
#pragma unroll
            for (int mi = 0; mi < 2; mi++) {
                int r = wm*32 + mi*16 + gid;
                float2 lo = *(const float2*)&As[r*40     + ks*8 + 2*q4];
                float2 hi = *(const float2*)&As[(r+8)*40 + ks*8 + 2*q4];
                a[mi][0] = __float_as_uint(lo.x);
                a[mi][1] = __float_as_uint(hi.x);
                a[mi][2] = __float_as_uint(lo.y);
                a[mi][3] = __float_as_uint(hi.y);
            }
#pragma unroll
            for (int ni = 0; ni < 4; ni++) {
                int rb = wn*32 + ni*8 + gid;
                float2 bb = *(const float2*)&Bs[rb*40 + ks*8 + 2*q4];
                unsigned b[2] = { __float_as_uint(bb.x), __float_as_uint(bb.y) };
                mma_tf32(acc[0][ni], a[0], b);
                mma_tf32(acc[1][ni], a[1], b);
            }
        }
    }

    // epilogue: + bias + residual
#pragma unroll
    for (int mi = 0; mi < 2; mi++) {
#pragma unroll
        for (int ni = 0; ni < 4; ni++) {
            int c0 = n0 + wn*32 + ni*8 + 2*q4;
            float2 bias2 = *(const float2*)(bfc + c0);
#pragma unroll
            for (int rr = 0; rr < 2; rr++) {
                int m = m0 + wm*32 + mi*16 + gid + rr*8;
                float2 res = *(const float2*)(qres + (size_t)m*DM + c0);
                float2 v;
                v.x = acc[mi][ni][rr*2 + 0] + bias2.x + res.x;
                v.y = acc[mi][ni][rr*2 + 1] + bias2.y + res.y;
                *(float2*)(g_X + (size_t)m*DM + c0) = v;
            }
        }
    }
}

// ---------------- LayerNorm: one warp per 512-elem row ---------------------
__global__ __launch_bounds__(256) void ln_kernel(const float* __restrict__ gamma,
                                                 const float* __restrict__ beta,
                                                 float* __restrict__ out) {
    const int gw = (blockIdx.x * blockDim.x + threadIdx.x) >> 5;
    const int lane = threadIdx.x & 31;
    if (gw >= MROWS) return;

    const float4* xp = (const float4*)(g_X + (size_t)gw * DM);
    float4 v[4];
#pragma unroll
    for (int i = 0; i < 4; i++) v[i] = xp[lane + 32*i];

    float sum = 0.f;
#pragma unroll
    for (int i = 0; i < 4; i++) sum += v[i].x + v[i].y + v[i].z + v[i].w;
#pragma unroll
    for (int o = 16; o; o >>= 1) sum += __shfl_xor_sync(0xffffffffu, sum, o);
    const float mean = sum * (1.0f / DM);

    float sq = 0.f;
#pragma unroll
    for (int i = 0; i < 4; i++) {
        float dx = v[i].x - mean, dy = v[i].y - mean;
        float dz = v[i].z - mean, dw = v[i].w - mean;
        sq += dx*dx + dy*dy + dz*dz + dw*dw;
    }
#pragma unroll
    for (int o = 16; o; o >>= 1) sq += __shfl_xor_sync(0xffffffffu, sq, o);
    const float rstd = rsqrtf(sq * (1.0f / DM) + 1e-5f);

    const float4* gp = (const float4*)gamma;
    const float4* bp = (const float4*)beta;
    float4* op = (float4*)(out + (size_t)gw * DM);
#pragma unroll
    for (int i = 0; i < 4; i++) {
        float4 g = gp[lane + 32*i];
        float4 b = bp[lane + 32*i];
        float4 r;
        r.x = (v[i].x - mean) * rstd * g.x + b.x;
        r.y = (v[i].y - mean) * rstd * g.y + b.y;
        r.z = (v[i].z - mean) * rstd * g.z + b.z;
        r.w = (v[i].w - mean) * rstd * g.w + b.w;
        op[lane + 32*i] = r;
    }
}

// ---------------- launch ---------------------------------------------------
extern "C" void kernel_launch(void* const* d_in, const int* in_sizes, int n_in,
                              void* d_out, int out_size) {
    const float* q     = (const float*)d_in[0];
    const float* k     = (const float*)d_in[1];
    const float* v     = (const float*)d_in[2];
    const float* Wq    = (const float*)d_in[3];
    const float* bq    = (const float*)d_in[4];
    const float* Wk    = (const float*)d_in[5];
    const float* bk    = (const float*)d_in[6];
    const float* Wv    = (const float*)d_in[7];
    const float* bv    = (const float*)d_in[8];
    const float* Wfc   = (const float*)d_in[9];
    const float* bfc   = (const float*)d_in[10];
    const float* gamma = (const float*)d_in[11];
    const float* beta  = (const float*)d_in[12];

    dim3 gp(INNER/64, MROWS/128, 3);      // (4, 64, 3)
    proj_mma<<<gp, 256>>>(q, k, v, Wq, Wk, Wv, bq, bk, bv);

    dim3 ga(LSEQ/128, HN, BSZ);           // (16, 8, 4)
    attn_f16<<<ga, 256>>>();

    dim3 gf(DM/64, MROWS/128);            // (8, 64)
    fc_mma<<<gf, 256>>>(Wfc, bfc, q);

    ln_kernel<<<MROWS/8, 256>>>(gamma, beta, (float*)d_out);
}

// round 5
// speedup vs baseline: 3.6361x; 1.0350x over previous
#include <cuda_runtime.h>
#include <cuda_fp16.h>
#include <math.h>

#define DM   512
#define HN   8
#define DKH  32
#define BSZ  4
#define LSEQ 2048
#define INNER 256            // HN*DKH
#define MROWS (BSZ*LSEQ)     // 8192

// Q pre-scale: 1/sqrt(32) * log2(e)  (softmax runs in exp2 domain)
#define QSCALE (0.17677669529663687f * 1.4426950408889634f)

// ---------------- scratch (device globals; no allocation allowed) ----------
__device__ __half g_Qh[BSZ*HN*LSEQ*DKH];  // [n][h][l][d], pre-scaled, fp16
__device__ __half g_Kh[BSZ*HN*LSEQ*DKH];  // fp16
__device__ __half g_Vh[BSZ*HN*LSEQ*DKH];  // fp16
__device__ __half g_AOh[MROWS*INNER];     // attn out [m][h*32+d], fp16
__device__ float  g_X [MROWS*DM];         // fc + residual (LN input)

// ---------------- helpers ----------------------------------------------
__device__ __forceinline__ float ex2(float x) {
    float r;
    asm("ex2.approx.f32 %0, %1;" : "=f"(r) : "f"(x));
    return r;
}
__device__ __forceinline__ unsigned pack_h2(float lo, float hi) {
    __half2 h = __floats2half2_rn(lo, hi);      // x = lo, y = hi
    return *(unsigned*)&h;
}

__device__ __forceinline__ void mma_f16(float c[4], const unsigned a[4],
                                        unsigned b0, unsigned b1) {
    asm volatile(
        "mma.sync.aligned.m16n8k16.row.col.f32.f16.f16.f32 "
        "{%0,%1,%2,%3}, {%4,%5,%6,%7}, {%8,%9}, {%0,%1,%2,%3};"
        : "+f"(c[0]), "+f"(c[1]), "+f"(c[2]), "+f"(c[3])
        : "r"(a[0]), "r"(a[1]), "r"(a[2]), "r"(a[3]),
          "r"(b0), "r"(b1));
}

// interleave position of word w (0..15) within a 16-word K-chunk:
// groups of 8 words; within a group, pairs (j, j+4) become adjacent.
__device__ __forceinline__ int wpos(int w) {
    return (w & 8) + 2*(w & 3) + ((w >> 2) & 1);
}

// ---------------- fused projection GEMM (fp16 mma, fp32 acc) ---------------
// C[M=8192, N=256] = X @ W^T + b, scattered head-major as fp16.
// CTA tile 128x64, 256 threads (8 warps: 4M x 2N, warp tile 32x32). BK=32.
__global__ __launch_bounds__(256) void proj_mma(
        const float* __restrict__ xq, const float* __restrict__ xk, const float* __restrict__ xv,
        const float* __restrict__ Wq, const float* __restrict__ Wk, const float* __restrict__ Wv,
        const float* __restrict__ bq, const float* __restrict__ bk, const float* __restrict__ bv) {
    const int which = blockIdx.z;
    const float* X    = (which == 0) ? xq : (which == 1) ? xk : xv;
    const float* W    = (which == 0) ? Wq : (which == 1) ? Wk : Wv;
    const float* bias = (which == 0) ? bq : (which == 1) ? bk : bv;
    __half* Out       = (which == 0) ? g_Qh : (which == 1) ? g_Kh : g_Vh;
    const float oscale = (which == 0) ? QSCALE : 1.0f;

    __shared__ unsigned As[128*40];   // [row][16 half2 words interleaved], stride 40
    __shared__ unsigned Bs[64*40];

    const int t = threadIdx.x;
    const int m0 = blockIdx.y * 128, n0 = blockIdx.x * 64;
    const int warp = t >> 5, lane = t & 31;
    const int gid = lane >> 2, q4 = lane & 3;
    const int wm = warp & 3, wn = warp >> 2;

    // staging maps
    const int aRow = t >> 1, aHalf = (t & 1) * 16;   // 16 floats per thread
    const int bRow = t >> 2, bQ    = (t & 3) * 8;    // 8 floats per thread

    float4 aR[4]; float4 bR[2];
#pragma unroll
    for (int j = 0; j < 4; j++)
        aR[j] = *(const float4*)(X + (size_t)(m0 + aRow)*DM + aHalf + 4*j);
#pragma unroll
    for (int j = 0; j < 2; j++)
        bR[j] = *(const float4*)(W + (size_t)(n0 + bRow)*DM + bQ + 4*j);

    float acc[2][4][4] = {};

    const int NIT = DM / 32;    // 16
    for (int it = 0; it < NIT; it++) {
        __syncthreads();
        {   // pack fp32 -> half2 words, store interleaved
            unsigned wv[8];
#pragma unroll
            for (int j = 0; j < 4; j++) {
                wv[2*j]   = pack_h2(aR[j].x, aR[j].y);
                wv[2*j+1] = pack_h2(aR[j].z, aR[j].w);
            }
#pragma unroll
            for (int j = 0; j < 8; j++)
                As[aRow*40 + wpos((aHalf >> 1) + j)] = wv[j];
            unsigned bw[4];
            bw[0] = pack_h2(bR[0].x, bR[0].y);
            bw[1] = pack_h2(bR[0].z, bR[0].w);
            bw[2] = pack_h2(bR[1].x, bR[1].y);
            bw[3] = pack_h2(bR[1].z, bR[1].w);
#pragma unroll
            for (int j = 0; j < 4; j++)
                Bs[bRow*40 + wpos((bQ >> 1) + j)] = bw[j];
        }
        __syncthreads();
        if (it + 1 < NIT) {
            int k0 = (it + 1) * 32;
#pragma unroll
            for (int j = 0; j < 4; j++)
                aR[j] = *(const float4*)(X + (size_t)(m0 + aRow)*DM + k0 + aHalf + 4*j);
#pragma unroll
            for (int j = 0; j < 2; j++)
                bR[j] = *(const float4*)(W + (size_t)(n0 + bRow)*DM + k0 + bQ + 4*j);
        }
#pragma unroll
        for (int ks = 0; ks < 2; ks++) {       // two k16 steps
            unsigned a[2][4];
#pragma unroll
            for (int mi = 0; mi < 2; mi++) {
                int r = wm*32 + mi*16 + gid;
                uint2 lo = *(const uint2*)&As[r*40     + ks*8 + 2*q4];
                uint2 hi = *(const uint2*)&As[(r+8)*40 + ks*8 + 2*q4];
                a[mi][0] = lo.x; a[mi][1] = hi.x;
                a[mi][2] = lo.y; a[mi][3] = hi.y;
            }
#pragma unroll
            for (int ni = 0; ni < 4; ni++) {
                int rb = wn*32 + ni*8 + gid;
                uint2 bb = *(const uint2*)&Bs[rb*40 + ks*8 + 2*q4];
                mma_f16(acc[0][ni], a[0], bb.x, bb.y);
                mma_f16(acc[1][ni], a[1], bb.x, bb.y);
            }
        }
    }

    // epilogue: scatter head-major fp16  Out[n][h][l][d],  c = d*8 + h
#pragma unroll
    for (int mi = 0; mi < 2; mi++) {
#pragma unroll
        for (int ni = 0; ni < 4; ni++) {
            int r0 = m0 + wm*32 + mi*16 + gid;
            int c0 = n0 + wn*32 + ni*8 + 2*q4;
#pragma unroll
            for (int rr = 0; rr < 2; rr++) {
#pragma unroll
                for (int cc = 0; cc < 2; cc++) {
                    int m = r0 + rr*8, c = c0 + cc;
                    float v = (acc[mi][ni][rr*2 + cc] + __ldg(bias + c)) * oscale;
                    int nb = m >> 11, l = m & 2047;
                    int d = c >> 3, hh = c & 7;
                    Out[((((size_t)nb*HN + hh)*LSEQ + l)*DKH) + d] = __float2half_rn(v);
                }
            }
        }
    }
}

// ---------------- flash attention (fp16 mma, fp32 acc, zero-shuffle P) -----
// CTA = one (n,h), 128 queries; 8 warps x 16 queries. 64-key tiles.
__global__ __launch_bounds__(256) void attn_f16() {
    const int n = blockIdx.z, h = blockIdx.y;
    const int tid  = threadIdx.x;
    const int warp = tid >> 5, lane = tid & 31;
    const int gid  = lane >> 2, q4 = lane & 3;
    const int qbase = blockIdx.x * 128 + warp * 16;

    const size_t slab = (((size_t)n*HN + h) * LSEQ) * DKH;
    const __half* Qg = g_Qh + slab;
    const __half* Kg = g_Kh + slab;
    const __half* Vg = g_Vh + slab;

    // Ksm: [64 keys][16 words of half2 (d pairs), interleaved, stride 24]
    // Vsm: [32 d][32 words of half2 (key pairs), interleaved, stride 40]
    __shared__ unsigned Ksm[64*24];
    __shared__ unsigned Vsm[32*40];

    // ---- Q fragments (already scaled + fp16 in gmem) ----
    unsigned qa[2][4];
    {
        const __half* qp  = Qg + (size_t)(qbase + gid) * 32;
        const __half* qp8 = qp + 8*32;
#pragma unroll
        for (int kk = 0; kk < 2; kk++) {
            qa[kk][0] = *(const unsigned*)(qp  + kk*16 + 2*q4);
            qa[kk][1] = *(const unsigned*)(qp8 + kk*16 + 2*q4);
            qa[kk][2] = *(const unsigned*)(qp  + kk*16 + 2*q4 + 8);
            qa[kk][3] = *(const unsigned*)(qp8 + kk*16 + 2*q4 + 8);
        }
    }

    float o[4][4] = {};
    float mrow[2] = {-1e30f, -1e30f};
    float lrow[2] = {0.f, 0.f};

    // staging thread mapping
    const int kKey = tid >> 2;              // K: key row (0..63)
    const int kW   = (tid & 3) * 4;         // K: first of 4 words
    const int vKp  = tid & 31;              // V: key pair (0..31)
    const int vD   = (tid >> 5) * 4;        // V: d base (0..28)
    const int vpos = (vKp & 24) + 2*(vKp & 3) + ((vKp >> 2) & 1);

    // preload tile 0 into regs
    uint4 kR = ((const uint4*)Kg)[tid];
    uint2 vA = *(const uint2*)(Vg + (size_t)(2*vKp    )*32 + vD);
    uint2 vB = *(const uint2*)(Vg + (size_t)(2*vKp + 1)*32 + vD);

    for (int kt = 0; kt < LSEQ; kt += 64) {
        __syncthreads();
        {   // store staged regs -> smem (interleaved layouts)
            unsigned kv[4] = {kR.x, kR.y, kR.z, kR.w};
#pragma unroll
            for (int c = 0; c < 4; c++) {
                int w = kW + c;
                int p = (w & 8) + 2*(w & 3) + ((w >> 2) & 1);
                Ksm[kKey*24 + p] = kv[c];
            }
            Vsm[(vD+0)*40 + vpos] = __byte_perm(vA.x, vB.x, 0x5410);
            Vsm[(vD+1)*40 + vpos] = __byte_perm(vA.x, vB.x, 0x7632);
            Vsm[(vD+2)*40 + vpos] = __byte_perm(vA.y, vB.y, 0x5410);
            Vsm[(vD+3)*40 + vpos] = __byte_perm(vA.y, vB.y, 0x7632);
        }
        __syncthreads();
        if (kt + 64 < LSEQ) {   // prefetch next tile
            kR = ((const uint4*)(Kg + (size_t)(kt + 64)*32))[tid];
            vA = *(const uint2*)(Vg + (size_t)(kt + 64 + 2*vKp    )*32 + vD);
            vB = *(const uint2*)(Vg + (size_t)(kt + 64 + 2*vKp + 1)*32 + vD);
        }

        // ---- S = Q K^T (log2 domain; scale folded into Q) ----
        float s[8][4] = {};
#pragma unroll
        for (int ni = 0; ni < 8; ni++) {
            const unsigned* kr = &Ksm[(ni*8 + gid)*24 + 2*q4];
#pragma unroll
            for (int kk = 0; kk < 2; kk++) {
                uint2 b = *(const uint2*)(kr + kk*8);
                mma_f16(s[ni], qa[kk], b.x, b.y);
            }
        }

        // ---- online softmax (exp2) ----
#pragma unroll
        for (int rh = 0; rh < 2; rh++) {
            float tmax = -1e30f;
#pragma unroll
            for (int ni = 0; ni < 8; ni++)
                tmax = fmaxf(tmax, fmaxf(s[ni][2*rh], s[ni][2*rh+1]));
            tmax = fmaxf(tmax, __shfl_xor_sync(0xffffffffu, tmax, 1));
            tmax = fmaxf(tmax, __shfl_xor_sync(0xffffffffu, tmax, 2));
            float mnew = fmaxf(mrow[rh], tmax);
            float corr = ex2(mrow[rh] - mnew);
            mrow[rh] = mnew;
            float lsum = lrow[rh] * corr;
#pragma unroll
            for (int nv = 0; nv < 4; nv++) {
                o[nv][2*rh]   *= corr;
                o[nv][2*rh+1] *= corr;
            }
#pragma unroll
            for (int ni = 0; ni < 8; ni++) {
                float p0 = ex2(s[ni][2*rh]   - mnew);
                float p1 = ex2(s[ni][2*rh+1] - mnew);
                lsum += p0 + p1;
                s[ni][2*rh]   = p0;
                s[ni][2*rh+1] = p1;
            }
            lrow[rh] = lsum;
        }

        // ---- O += P V : accumulator layout == A layout for f16 (pack only) ----
#pragma unroll
        for (int kc = 0; kc < 4; kc++) {
            unsigned pa[4];
            pa[0] = pack_h2(s[2*kc  ][0], s[2*kc  ][1]);
            pa[1] = pack_h2(s[2*kc  ][2], s[2*kc  ][3]);
            pa[2] = pack_h2(s[2*kc+1][0], s[2*kc+1][1]);
            pa[3] = pack_h2(s[2*kc+1][2], s[2*kc+1][3]);
#pragma unroll
            for (int nv = 0; nv < 4; nv++) {
                uint2 b = *(const uint2*)&Vsm[(nv*8 + gid)*40 + kc*8 + 2*q4];
                mma_f16(o[nv], pa, b.x, b.y);
            }
        }
    }

    // ---- epilogue: finish row sums, normalize, write fp16 ----
    float inv[2];
#pragma unroll
    for (int rh = 0; rh < 2; rh++) {
        float l = lrow[rh];
        l += __shfl_xor_sync(0xffffffffu, l, 1);
        l += __shfl_xor_sync(0xffffffffu, l, 2);
        inv[rh] = 1.0f / l;
    }
#pragma unroll
    for (int rh = 0; rh < 2; rh++) {
        int row = qbase + rh*8 + gid;
        float iv = inv[rh];
#pragma unroll
        for (int nv = 0; nv < 4; nv++) {
            int col = h*32 + nv*8 + q4*2;
            *(unsigned*)(g_AOh + ((size_t)n*LSEQ + row)*INNER + col)
                = pack_h2(o[nv][2*rh] * iv, o[nv][2*rh+1] * iv);
        }
    }
}

// ---------------- FC GEMM (fp16 mma) + bias + residual ---------------------
// X[M=8192, N=512] = AOh[M,256] @ Wfc^T + bfc + q
__global__ __launch_bounds__(256) void fc_mma(const float* __restrict__ Wfc,
                                              const float* __restrict__ bfc,
                                              const float* __restrict__ qres) {
    __shared__ unsigned As[128*40];
    __shared__ unsigned Bs[64*40];

    const int t = threadIdx.x;
    const int m0 = blockIdx.y * 128, n0 = blockIdx.x * 64;
    const int warp = t >> 5, lane = t & 31;
    const int gid = lane >> 2, q4 = lane & 3;
    const int wm = warp & 3, wn = warp >> 2;

    const int aRow = t >> 1, aW = (t & 1) * 8;       // 8 words (16 halves)
    const int bRow = t >> 2, bQ = (t & 3) * 8;       // 8 floats

    // A is already fp16 in gmem
    uint4 aR[2]; float4 bR[2];
#pragma unroll
    for (int j = 0; j < 2; j++)
        aR[j] = *(const uint4*)((const unsigned*)(g_AOh + (size_t)(m0 + aRow)*INNER) + aW + 4*j);
#pragma unroll
    for (int j = 0; j < 2; j++)
        bR[j] = *(const float4*)(Wfc + (size_t)(n0 + bRow)*INNER + bQ + 4*j);

    float acc[2][4][4] = {};
    const int NIT = INNER / 32;   // 8
    for (int it = 0; it < NIT; it++) {
        __syncthreads();
        {
            unsigned wv[8] = {aR[0].x, aR[0].y, aR[0].z, aR[0].w,
                              aR[1].x, aR[1].y, aR[1].z, aR[1].w};
#pragma unroll
            for (int j = 0; j < 8; j++)
                As[aRow*40 + wpos(aW + j)] = wv[j];
            unsigned bw[4];
            bw[0] = pack_h2(bR[0].x, bR[0].y);
            bw[1] = pack_h2(bR[0].z, bR[0].w);
            bw[2] = pack_h2(bR[1].x, bR[1].y);
            bw[3] = pack_h2(bR[1].z, bR[1].w);
#pragma unroll
            for (int j = 0; j < 4; j++)
                Bs[bRow*40 + wpos((bQ >> 1) + j)] = bw[j];
        }
        __syncthreads();
        if (it + 1 < NIT) {
            int k0 = (it + 1) * 32;
#pragma unroll
            for (int j = 0; j < 2; j++)
                aR[j] = *(const uint4*)((const unsigned*)(g_AOh + (size_t)(m0 + aRow)*INNER + k0) + aW + 4*j);
#pragma unroll
            for (int j = 0; j < 2; j++)
                bR[j] = *(const float4*)(Wfc + (size_t)(n0 + bRow)*INNER + k0 + bQ + 4*j);
        }
#pragma unroll
        for (int ks = 0; ks < 2; ks++) {
            unsigned a[2][4];
#pragma unroll
            for (int mi = 0; mi < 2; mi++) {
                int r = wm*32 + mi*16 + gid;
                uint2 lo = *(const uint2*)&As[r*40     + ks*8 + 2*q4];
                uint2 hi = *(const uint2*)&As[(r+8)*40 + ks*8 + 2*q4];
                a[mi][0] = lo.x; a[mi][1] = hi.x;
                a[mi][2] = lo.y; a[mi][3] = hi.y;
            }
#pragma unroll
            for (int ni = 0; ni < 4; ni++) {
                int rb = wn*32 + ni*8 + gid;
                uint2 bb = *(const uint2*)&Bs[rb*40 + ks*8 + 2*q4];
                mma_f16(acc[0][ni], a[0], bb.x, bb.y);
                mma_f16(acc[1][ni], a[1], bb.x, bb.y);
            }
        }
    }

    // epilogue: + bias + residual (fp32)
#pragma unroll
    for (int mi = 0; mi < 2; mi++) {
#pragma unroll
        for (int ni = 0; ni < 4; ni++) {
            int c0 = n0 + wn*32 + ni*8 + 2*q4;
            float2 bias2 = *(const float2*)(bfc + c0);
#pragma unroll
            for (int rr = 0; rr < 2; rr++) {
                int m = m0 + wm*32 + mi*16 + gid + rr*8;
                float2 res = *(const float2*)(qres + (size_t)m*DM + c0);
                float2 v;
                v.x = acc[mi][ni][rr*2 + 0] + bias2.x + res.x;
                v.y = acc[mi][ni][rr*2 + 1] + bias2.y + res.y;
                *(float2*)(g_X + (size_t)m*DM + c0) = v;
            }
        }
    }
}

// ---------------- LayerNorm: one warp per 512-elem row ---------------------
__global__ __launch_bounds__(256) void ln_kernel(const float* __restrict__ gamma,
                                                 const float* __restrict__ beta,
                                                 float* __restrict__ out) {
    const int gw = (blockIdx.x * blockDim.x + threadIdx.x) >> 5;
    const int lane = threadIdx.x & 31;
    if (gw >= MROWS) return;

    const float4* xp = (const float4*)(g_X + (size_t)gw * DM);
    float4 v[4];
#pragma unroll
    for (int i = 0; i < 4; i++) v[i] = xp[lane + 32*i];

    float sum = 0.f;
#pragma unroll
    for (int i = 0; i < 4; i++) sum += v[i].x + v[i].y + v[i].z + v[i].w;
#pragma unroll
    for (int o = 16; o; o >>= 1) sum += __shfl_xor_sync(0xffffffffu, sum, o);
    const float mean = sum * (1.0f / DM);

    float sq = 0.f;
#pragma unroll
    for (int i = 0; i < 4; i++) {
        float dx = v[i].x - mean, dy = v[i].y - mean;
        float dz = v[i].z - mean, dw = v[i].w - mean;
        sq += dx*dx + dy*dy + dz*dz + dw*dw;
    }
#pragma unroll
    for (int o = 16; o; o >>= 1) sq += __shfl_xor_sync(0xffffffffu, sq, o);
    const float rstd = rsqrtf(sq * (1.0f / DM) + 1e-5f);

    const float4* gp = (const float4*)gamma;
    const float4* bp = (const float4*)beta;
    float4* op = (float4*)(out + (size_t)gw * DM);
#pragma unroll
    for (int i = 0; i < 4; i++) {
        float4 g = gp[lane + 32*i];
        float4 b = bp[lane + 32*i];
        float4 r;
        r.x = (v[i].x - mean) * rstd * g.x + b.x;
        r.y = (v[i].y - mean) * rstd * g.y + b.y;
        r.z = (v[i].z - mean) * rstd * g.z + b.z;
        r.w = (v[i].w - mean) * rstd * g.w + b.w;
        op[lane + 32*i] = r;
    }
}

// ---------------- launch ---------------------------------------------------
extern "C" void kernel_launch(void* const* d_in, const int* in_sizes, int n_in,
                              void* d_out, int out_size) {
    const float* q     = (const float*)d_in[0];
    const float* k     = (const float*)d_in[1];
    const float* v     = (const float*)d_in[2];
    const float* Wq    = (const float*)d_in[3];
    const float* bq    = (const float*)d_in[4];
    const float* Wk    = (const float*)d_in[5];
    const float* bk    = (const float*)d_in[6];
    const float* Wv    = (const float*)d_in[7];
    const float* bv    = (const float*)d_in[8];
    const float* Wfc   = (const float*)d_in[9];
    const float* bfc   = (const float*)d_in[10];
    const float* gamma = (const float*)d_in[11];
    const float* beta  = (const float*)d_in[12];

    dim3 gp(INNER/64, MROWS/128, 3);      // (4, 64, 3)
    proj_mma<<<gp, 256>>>(q, k, v, Wq, Wk, Wv, bq, bk, bv);

    dim3 ga(LSEQ/128, HN, BSZ);           // (16, 8, 4)
    attn_f16<<<ga, 256>>>();

    dim3 gf(DM/64, MROWS/128);            // (8, 64)
    fc_mma<<<gf, 256>>>(Wfc, bfc, q);

    ln_kernel<<<MROWS/8, 256>>>(gamma, beta, (float*)d_out);
}

// round 6
// speedup vs baseline: 5.1106x; 1.4055x over previous
#include <cuda_runtime.h>
#include <cuda_fp16.h>
#include <math.h>

#define DM   512
#define HN   8
#define DKH  32
#define BSZ  4
#define LSEQ 2048
#define INNER 256            // HN*DKH
#define MROWS (BSZ*LSEQ)     // 8192

// Q pre-scale: 1/sqrt(32) * log2(e)  (softmax runs in exp2 domain)
#define QSCALE (0.17677669529663687f * 1.4426950408889634f)

// ---------------- scratch (device globals; no allocation allowed) ----------
__device__ __half g_Qh[BSZ*HN*LSEQ*DKH];  // [n][h][l][d], pre-scaled, fp16
__device__ __half g_Kh[BSZ*HN*LSEQ*DKH];  // fp16
__device__ __half g_Vh[BSZ*HN*LSEQ*DKH];  // fp16
__device__ __half g_AOh[MROWS*INNER];     // attn out [m][h*32+d], fp16
__device__ float  g_X [MROWS*DM];         // fc + residual (LN input)
__device__ __half g_Wh  [3*INNER*DM];     // Wq|Wk|Wv fp16, [256][512] each
__device__ __half g_Wfch[DM*INNER];       // Wfc fp16 [512][256]

// ---------------- helpers ----------------------------------------------
__device__ __forceinline__ float ex2(float x) {
    float r;
    asm("ex2.approx.f32 %0, %1;" : "=f"(r) : "f"(x));
    return r;
}
__device__ __forceinline__ unsigned pack_h2(float lo, float hi) {
    __half2 h = __floats2half2_rn(lo, hi);      // x = lo, y = hi
    return *(unsigned*)&h;
}

__device__ __forceinline__ void mma_f16(float c[4], const unsigned a[4],
                                        unsigned b0, unsigned b1) {
    asm volatile(
        "mma.sync.aligned.m16n8k16.row.col.f32.f16.f16.f32 "
        "{%0,%1,%2,%3}, {%4,%5,%6,%7}, {%8,%9}, {%0,%1,%2,%3};"
        : "+f"(c[0]), "+f"(c[1]), "+f"(c[2]), "+f"(c[3])
        : "r"(a[0]), "r"(a[1]), "r"(a[2]), "r"(a[3]),
          "r"(b0), "r"(b1));
}

// interleave position of word w (0..15) within a 16-word K-chunk:
// groups of 8 words; within a group, pairs (j, j+4) become adjacent.
__device__ __forceinline__ int wpos(int w) {
    return (w & 8) + 2*(w & 3) + ((w >> 2) & 1);
}

// ---------------- one-shot weight conversion fp32 -> fp16 ------------------
__global__ __launch_bounds__(256) void cvt_w(const float* __restrict__ Wq,
                                             const float* __restrict__ Wk,
                                             const float* __restrict__ Wv,
                                             const float* __restrict__ Wfc) {
    const int NW = INNER*DM/4;    // 32768 float4 per weight matrix
    int i = blockIdx.x * blockDim.x + threadIdx.x;
    if (i >= 4*NW) return;
    int which = i / NW, off = i - which*NW;
    const float* src = (which == 0) ? Wq : (which == 1) ? Wk : (which == 2) ? Wv : Wfc;
    float4 v = ((const float4*)src)[off];
    uint2 o;
    o.x = pack_h2(v.x, v.y);
    o.y = pack_h2(v.z, v.w);
    if (which < 3) ((uint2*)g_Wh)[(size_t)which*NW + off] = o;
    else           ((uint2*)g_Wfch)[off] = o;
}

// ---------------- projection GEMM: single-pass A ---------------------------
// CTA = 64 M-rows x full N=256. 256 threads, 8 warps (2M x 4N, warp 32x64).
// A (fp32 input) read from DRAM exactly once. B = fp16 weights (L2-hot).
__global__ __launch_bounds__(256) void proj_mma(
        const float* __restrict__ xq, const float* __restrict__ xk, const float* __restrict__ xv,
        const float* __restrict__ bq, const float* __restrict__ bk, const float* __restrict__ bv) {
    const int which = blockIdx.z;
    const float* X    = (which == 0) ? xq : (which == 1) ? xk : xv;
    const float* bias = (which == 0) ? bq : (which == 1) ? bk : bv;
    const __half* Wh  = g_Wh + (size_t)which * INNER * DM;
    __half* Out       = (which == 0) ? g_Qh : (which == 1) ? g_Kh : g_Vh;
    const float oscale = (which == 0) ? QSCALE : 1.0f;

    __shared__ unsigned As[64*24];    // 64 rows x 16 words (interleaved, stride 24)
    __shared__ unsigned Bs[256*24];
    __shared__ float bsm[INNER];

    const int t = threadIdx.x;
    const int m0 = blockIdx.x * 64;
    const int warp = t >> 5, lane = t & 31;
    const int gid = lane >> 2, q4 = lane & 3;
    const int wm = warp >> 2, wn = warp & 3;

    bsm[t] = bias[t];

    // staging maps
    const int aRow = t >> 2, aq = t & 3;     // A: 8 fp32 per thread per iter

    float4 aR[2]; uint4 bR[4];
#pragma unroll
    for (int j = 0; j < 2; j++)
        aR[j] = *(const float4*)(X + (size_t)(m0 + aRow)*DM + aq*8 + 4*j);
#pragma unroll
    for (int j = 0; j < 4; j++) {
        int i = t + 256*j;
        bR[j] = *(const uint4*)(Wh + (size_t)(i >> 2)*DM + (i & 3)*8);
    }

    float acc[2][8][4] = {};

    const int NIT = DM / 32;    // 16
    for (int it = 0; it < NIT; it++) {
        __syncthreads();
        {
            unsigned wv[4];
            wv[0] = pack_h2(aR[0].x, aR[0].y);
            wv[1] = pack_h2(aR[0].z, aR[0].w);
            wv[2] = pack_h2(aR[1].x, aR[1].y);
            wv[3] = pack_h2(aR[1].z, aR[1].w);
#pragma unroll
            for (int c = 0; c < 4; c++)
                As[aRow*24 + wpos(4*aq + c)] = wv[c];
#pragma unroll
            for (int j = 0; j < 4; j++) {
                int i = t + 256*j;
                int row = i >> 2, q = i & 3;
                unsigned bw[4] = {bR[j].x, bR[j].y, bR[j].z, bR[j].w};
#pragma unroll
                for (int c = 0; c < 4; c++)
                    Bs[row*24 + wpos(4*q + c)] = bw[c];
            }
        }
        __syncthreads();
        if (it + 1 < NIT) {
            int k0 = (it + 1) * 32;
#pragma unroll
            for (int j = 0; j < 2; j++)
                aR[j] = *(const float4*)(X + (size_t)(m0 + aRow)*DM + k0 + aq*8 + 4*j);
#pragma unroll
            for (int j = 0; j < 4; j++) {
                int i = t + 256*j;
                bR[j] = *(const uint4*)(Wh + (size_t)(i >> 2)*DM + k0 + (i & 3)*8);
            }
        }
#pragma unroll
        for (int ks = 0; ks < 2; ks++) {
            unsigned a[2][4];
#pragma unroll
            for (int mi = 0; mi < 2; mi++) {
                int r = wm*32 + mi*16 + gid;
                uint2 lo = *(const uint2*)&As[r*24      + ks*8 + 2*q4];
                uint2 hi = *(const uint2*)&As[(r+8)*24  + ks*8 + 2*q4];
                a[mi][0] = lo.x; a[mi][1] = hi.x;
                a[mi][2] = lo.y; a[mi][3] = hi.y;
            }
#pragma unroll
            for (int ni = 0; ni < 8; ni++) {
                int rb = wn*64 + ni*8 + gid;
                uint2 bb = *(const uint2*)&Bs[rb*24 + ks*8 + 2*q4];
                mma_f16(acc[0][ni], a[0], bb.x, bb.y);
                mma_f16(acc[1][ni], a[1], bb.x, bb.y);
            }
        }
    }

    // epilogue: head-major scatter; 8 consecutive d per STG.128
    // c = wn*64 + ni*8 + 2*q4 + cc  ->  d = wn*8 + ni (consecutive in ni), h = 2*q4+cc
#pragma unroll
    for (int mi = 0; mi < 2; mi++) {
#pragma unroll
        for (int rr = 0; rr < 2; rr++) {
            int m = m0 + wm*32 + mi*16 + rr*8 + gid;
            int nb = m >> 11, l = m & 2047;
#pragma unroll
            for (int cc = 0; cc < 2; cc++) {
                int h = 2*q4 + cc;
                float v[8];
#pragma unroll
                for (int ni = 0; ni < 8; ni++)
                    v[ni] = (acc[mi][ni][rr*2 + cc] + bsm[wn*64 + ni*8 + h]) * oscale;
                uint4 o;
                o.x = pack_h2(v[0], v[1]);
                o.y = pack_h2(v[2], v[3]);
                o.z = pack_h2(v[4], v[5]);
                o.w = pack_h2(v[6], v[7]);
                *(uint4*)(Out + ((((size_t)nb*HN + h)*LSEQ + l)*DKH) + wn*8) = o;
            }
        }
    }
}

// ---------------- flash attention (fp16 mma, h2exp2 softmax) ---------------
// CTA = one (n,h), 128 queries; 8 warps x 16 queries. 64-key tiles.
__global__ __launch_bounds__(256) void attn_f16() {
    const int n = blockIdx.z, h = blockIdx.y;
    const int tid  = threadIdx.x;
    const int warp = tid >> 5, lane = tid & 31;
    const int gid  = lane >> 2, q4 = lane & 3;
    const int qbase = blockIdx.x * 128 + warp * 16;

    const size_t slab = (((size_t)n*HN + h) * LSEQ) * DKH;
    const __half* Qg = g_Qh + slab;
    const __half* Kg = g_Kh + slab;
    const __half* Vg = g_Vh + slab;

    __shared__ unsigned Ksm[64*24];
    __shared__ unsigned Vsm[32*40];

    unsigned qa[2][4];
    {
        const __half* qp  = Qg + (size_t)(qbase + gid) * 32;
        const __half* qp8 = qp + 8*32;
#pragma unroll
        for (int kk = 0; kk < 2; kk++) {
            qa[kk][0] = *(const unsigned*)(qp  + kk*16 + 2*q4);
            qa[kk][1] = *(const unsigned*)(qp8 + kk*16 + 2*q4);
            qa[kk][2] = *(const unsigned*)(qp  + kk*16 + 2*q4 + 8);
            qa[kk][3] = *(const unsigned*)(qp8 + kk*16 + 2*q4 + 8);
        }
    }

    float o[4][4] = {};
    float mrow[2] = {-1e30f, -1e30f};
    float lrow[2] = {0.f, 0.f};

    const int kKey = tid >> 2;
    const int kW   = (tid & 3) * 4;
    const int vKp  = tid & 31;
    const int vD   = (tid >> 5) * 4;
    const int vpos = (vKp & 24) + 2*(vKp & 3) + ((vKp >> 2) & 1);

    uint4 kR = ((const uint4*)Kg)[tid];
    uint2 vA = *(const uint2*)(Vg + (size_t)(2*vKp    )*32 + vD);
    uint2 vB = *(const uint2*)(Vg + (size_t)(2*vKp + 1)*32 + vD);

    for (int kt = 0; kt < LSEQ; kt += 64) {
        __syncthreads();
        {
            unsigned kv[4] = {kR.x, kR.y, kR.z, kR.w};
#pragma unroll
            for (int c = 0; c < 4; c++) {
                int w = kW + c;
                Ksm[kKey*24 + wpos(w)] = kv[c];
            }
            Vsm[(vD+0)*40 + vpos] = __byte_perm(vA.x, vB.x, 0x5410);
            Vsm[(vD+1)*40 + vpos] = __byte_perm(vA.x, vB.x, 0x7632);
            Vsm[(vD+2)*40 + vpos] = __byte_perm(vA.y, vB.y, 0x5410);
            Vsm[(vD+3)*40 + vpos] = __byte_perm(vA.y, vB.y, 0x7632);
        }
        __syncthreads();
        if (kt + 64 < LSEQ) {
            kR = ((const uint4*)(Kg + (size_t)(kt + 64)*32))[tid];
            vA = *(const uint2*)(Vg + (size_t)(kt + 64 + 2*vKp    )*32 + vD);
            vB = *(const uint2*)(Vg + (size_t)(kt + 64 + 2*vKp + 1)*32 + vD);
        }

        // ---- S = Q K^T (log2 domain; scale folded into Q) ----
        float s[8][4] = {};
#pragma unroll
        for (int ni = 0; ni < 8; ni++) {
            const unsigned* kr = &Ksm[(ni*8 + gid)*24 + 2*q4];
#pragma unroll
            for (int kk = 0; kk < 2; kk++) {
                uint2 b = *(const uint2*)(kr + kk*8);
                mma_f16(s[ni], qa[kk], b.x, b.y);
            }
        }

        // ---- online softmax: fp32 max/subtract, h2exp2, fp32 sums ----
        unsigned p2[2][8];
#pragma unroll
        for (int rh = 0; rh < 2; rh++) {
            float tmax = -1e30f;
#pragma unroll
            for (int ni = 0; ni < 8; ni++)
                tmax = fmaxf(tmax, fmaxf(s[ni][2*rh], s[ni][2*rh+1]));
            tmax = fmaxf(tmax, __shfl_xor_sync(0xffffffffu, tmax, 1));
            tmax = fmaxf(tmax, __shfl_xor_sync(0xffffffffu, tmax, 2));
            float mnew = fmaxf(mrow[rh], tmax);
            float corr = ex2(mrow[rh] - mnew);
            mrow[rh] = mnew;
            float lsum = lrow[rh] * corr;
#pragma unroll
            for (int nv = 0; nv < 4; nv++) {
                o[nv][2*rh]   *= corr;
                o[nv][2*rh+1] *= corr;
            }
#pragma unroll
            for (int ni = 0; ni < 8; ni++) {
                __half2 dh = __floats2half2_rn(s[ni][2*rh] - mnew,
                                               s[ni][2*rh+1] - mnew);
                __half2 ph = h2exp2(dh);                 // one MUFU per pair
                p2[rh][ni] = *(unsigned*)&ph;
                float2 pf = __half22float2(ph);
                lsum += pf.x + pf.y;
            }
            lrow[rh] = lsum;
        }

        // ---- O += P V ----
#pragma unroll
        for (int kc = 0; kc < 4; kc++) {
            unsigned pa[4];
            pa[0] = p2[0][2*kc];
            pa[1] = p2[1][2*kc];
            pa[2] = p2[0][2*kc+1];
            pa[3] = p2[1][2*kc+1];
#pragma unroll
            for (int nv = 0; nv < 4; nv++) {
                uint2 b = *(const uint2*)&Vsm[(nv*8 + gid)*40 + kc*8 + 2*q4];
                mma_f16(o[nv], pa, b.x, b.y);
            }
        }
    }

    // ---- epilogue ----
    float inv[2];
#pragma unroll
    for (int rh = 0; rh < 2; rh++) {
        float l = lrow[rh];
        l += __shfl_xor_sync(0xffffffffu, l, 1);
        l += __shfl_xor_sync(0xffffffffu, l, 2);
        inv[rh] = 1.0f / l;
    }
#pragma unroll
    for (int rh = 0; rh < 2; rh++) {
        int row = qbase + rh*8 + gid;
        float iv = inv[rh];
#pragma unroll
        for (int nv = 0; nv < 4; nv++) {
            int col = h*32 + nv*8 + q4*2;
            *(unsigned*)(g_AOh + ((size_t)n*LSEQ + row)*INNER + col)
                = pack_h2(o[nv][2*rh] * iv, o[nv][2*rh+1] * iv);
        }
    }
}

// ---------------- FC GEMM: 64 x 256 tiles, A (fp16) + W (fp16) -------------
// X[M=8192, N=512] = AOh[M,256] @ Wfc^T + bfc + q ; grid (M/64, 2)
__global__ __launch_bounds__(256) void fc_mma(const float* __restrict__ bfc,
                                              const float* __restrict__ qres) {
    __shared__ unsigned As[64*24];
    __shared__ unsigned Bs[256*24];
    __shared__ float bsm[256];

    const int t = threadIdx.x;
    const int m0 = blockIdx.x * 64;
    const int n0 = blockIdx.y * 256;
    const int warp = t >> 5, lane = t & 31;
    const int gid = lane >> 2, q4 = lane & 3;
    const int wm = warp >> 2, wn = warp & 3;

    bsm[t] = bfc[n0 + t];

    const int aRow = t >> 2, aq = t & 3;

    uint4 aR; uint4 bR[4];
    aR = *(const uint4*)(g_AOh + (size_t)(m0 + aRow)*INNER + aq*8);
#pragma unroll
    for (int j = 0; j < 4; j++) {
        int i = t + 256*j;
        bR[j] = *(const uint4*)(g_Wfch + (size_t)(n0 + (i >> 2))*INNER + (i & 3)*8);
    }

    float acc[2][8][4] = {};

    const int NIT = INNER / 32;   // 8
    for (int it = 0; it < NIT; it++) {
        __syncthreads();
        {
            unsigned wv[4] = {aR.x, aR.y, aR.z, aR.w};
#pragma unroll
            for (int c = 0; c < 4; c++)
                As[aRow*24 + wpos(4*aq + c)] = wv[c];
#pragma unroll
            for (int j = 0; j < 4; j++) {
                int i = t + 256*j;
                int row = i >> 2, q = i & 3;
                unsigned bw[4] = {bR[j].x, bR[j].y, bR[j].z, bR[j].w};
#pragma unroll
                for (int c = 0; c < 4; c++)
                    Bs[row*24 + wpos(4*q + c)] = bw[c];
            }
        }
        __syncthreads();
        if (it + 1 < NIT) {
            int k0 = (it + 1) * 32;
            aR = *(const uint4*)(g_AOh + (size_t)(m0 + aRow)*INNER + k0 + aq*8);
#pragma unroll
            for (int j = 0; j < 4; j++) {
                int i = t + 256*j;
                bR[j] = *(const uint4*)(g_Wfch + (size_t)(n0 + (i >> 2))*INNER + k0 + (i & 3)*8);
            }
        }
#pragma unroll
        for (int ks = 0; ks < 2; ks++) {
            unsigned a[2][4];
#pragma unroll
            for (int mi = 0; mi < 2; mi++) {
                int r = wm*32 + mi*16 + gid;
                uint2 lo = *(const uint2*)&As[r*24     + ks*8 + 2*q4];
                uint2 hi = *(const uint2*)&As[(r+8)*24 + ks*8 + 2*q4];
                a[mi][0] = lo.x; a[mi][1] = hi.x;
                a[mi][2] = lo.y; a[mi][3] = hi.y;
            }
#pragma unroll
            for (int ni = 0; ni < 8; ni++) {
                int rb = wn*64 + ni*8 + gid;
                uint2 bb = *(const uint2*)&Bs[rb*24 + ks*8 + 2*q4];
                mma_f16(acc[0][ni], a[0], bb.x, bb.y);
                mma_f16(acc[1][ni], a[1], bb.x, bb.y);
            }
        }
    }

    // epilogue: + bias + residual (fp32)
#pragma unroll
    for (int mi = 0; mi < 2; mi++) {
#pragma unroll
        for (int rr = 0; rr < 2; rr++) {
            int m = m0 + wm*32 + mi*16 + rr*8 + gid;
#pragma unroll
            for (int ni = 0; ni < 8; ni++) {
                int cl = wn*64 + ni*8 + 2*q4;    // local col in [0,256)
                int c0 = n0 + cl;
                float2 res = *(const float2*)(qres + (size_t)m*DM + c0);
                float2 v;
                v.x = acc[mi][ni][rr*2 + 0] + bsm[cl]   + res.x;
                v.y = acc[mi][ni][rr*2 + 1] + bsm[cl+1] + res.y;
                *(float2*)(g_X + (size_t)m*DM + c0) = v;
            }
        }
    }
}

// ---------------- LayerNorm: one warp per 512-elem row ---------------------
__global__ __launch_bounds__(256) void ln_kernel(const float* __restrict__ gamma,
                                                 const float* __restrict__ beta,
                                                 float* __restrict__ out) {
    const int gw = (blockIdx.x * blockDim.x + threadIdx.x) >> 5;
    const int lane = threadIdx.x & 31;
    if (gw >= MROWS) return;

    const float4* xp = (const float4*)(g_X + (size_t)gw * DM);
    float4 v[4];
#pragma unroll
    for (int i = 0; i < 4; i++) v[i] = xp[lane + 32*i];

    float sum = 0.f;
#pragma unroll
    for (int i = 0; i < 4; i++) sum += v[i].x + v[i].y + v[i].z + v[i].w;
#pragma unroll
    for (int o = 16; o; o >>= 1) sum += __shfl_xor_sync(0xffffffffu, sum, o);
    const float mean = sum * (1.0f / DM);

    float sq = 0.f;
#pragma unroll
    for (int i = 0; i < 4; i++) {
        float dx = v[i].x - mean, dy = v[i].y - mean;
        float dz = v[i].z - mean, dw = v[i].w - mean;
        sq += dx*dx + dy*dy + dz*dz + dw*dw;
    }
#pragma unroll
    for (int o = 16; o; o >>= 1) sq += __shfl_xor_sync(0xffffffffu, sq, o);
    const float rstd = rsqrtf(sq * (1.0f / DM) + 1e-5f);

    const float4* gp = (const float4*)gamma;
    const float4* bp = (const float4*)beta;
    float4* op = (float4*)(out + (size_t)gw * DM);
#pragma unroll
    for (int i = 0; i < 4; i++) {
        float4 g = gp[lane + 32*i];
        float4 b = bp[lane + 32*i];
        float4 r;
        r.x = (v[i].x - mean) * rstd * g.x + b.x;
        r.y = (v[i].y - mean) * rstd * g.y + b.y;
        r.z = (v[i].z - mean) * rstd * g.z + b.z;
        r.w = (v[i].w - mean) * rstd * g.w + b.w;
        op[lane + 32*i] = r;
    }
}

// ---------------- launch ---------------------------------------------------
extern "C" void kernel_launch(void* const* d_in, const int* in_sizes, int n_in,
                              void* d_out, int out_size) {
    const float* q     = (const float*)d_in[0];
    const float* k     = (const float*)d_in[1];
    const float* v     = (const float*)d_in[2];
    const float* Wq    = (const float*)d_in[3];
    const float* bq    = (const float*)d_in[4];
    const float* Wk    = (const float*)d_in[5];
    const float* bk    = (const float*)d_in[6];
    const float* Wv    = (const float*)d_in[7];
    const float* bv    = (const float*)d_in[8];
    const float* Wfc   = (const float*)d_in[9];
    const float* bfc   = (const float*)d_in[10];
    const float* gamma = (const float*)d_in[11];
    const float* beta  = (const float*)d_in[12];

    cvt_w<<<512, 256>>>(Wq, Wk, Wv, Wfc);

    dim3 gp(MROWS/64, 1, 3);              // (128, 1, 3)
    proj_mma<<<gp, 256>>>(q, k, v, bq, bk, bv);

    dim3 ga(LSEQ/128, HN, BSZ);           // (16, 8, 4)
    attn_f16<<<ga, 256>>>();

    dim3 gf(MROWS/64, DM/256);            // (128, 2)
    fc_mma<<<gf, 256>>>(bfc, q);

    ln_kernel<<<MROWS/8, 256>>>(gamma, beta, (float*)d_out);
}